// round 14
// baseline (speedup 1.0000x reference)
#include <cuda_runtime.h>
#include <cuda_bf16.h>
#include <cuda_fp16.h>
#include <cstdint>

#define NN 50000
#define EE 800000
#define RR 5
#define DD 128
#define NTILE 391
#define NBKT (NN * RR)
#define SCAN_T 256
#define SCAN_ELT 8
#define SCAN_BLOCK (SCAN_T * SCAN_ELT)
#define NSCB ((NBKT + SCAN_BLOCK - 1) / SCAN_BLOCK)

// ---------------- device scratch ----------------
__device__ float  g_y[NN * DD];                 // encoder output (fp32)
__device__ __half g_x16[NN * DD];               // layer state ping
__device__ __half g_y16[NN * DD];               // layer state pong
__device__ __half g_Z[(size_t)RR * NN * DD];    // per-relation planes, fp16
__device__ int   g_bcnt[NBKT];
__device__ float g_inv[NBKT];
__device__ int   g_rp[NBKT + 1];
__device__ int   g_wpos[NBKT];
__device__ int   g_aux[256];
__device__ int   g_eidx[EE];    // et*NN + src
__device__ float g_esc[EE];     // inv[dst, et]

// encoder B fragment-ordered: [enc 2][chunk 24][512 words], bf16 hi/lo
__device__ uint32_t g_eBh[2 * 24 * 512];
__device__ uint32_t g_eBl[2 * 24 * 512];
// fragment-ordered fp16 B: chunks 0-4 rel_w, 5 root_w, 6 W_in, 7 W_o1; 8192 words each
#define FOFF_LAYER 0
#define FOFF_IN    (6 * 8192)
#define FOFF_O1    (7 * 8192)
__device__ uint32_t g_Bf[8 * 8192];

__device__ __forceinline__ float lrelu(float v) { return v > 0.f ? v : 0.01f * v; }

__device__ __forceinline__ void mma16816(float* d, const uint32_t* a, const uint32_t* b) {
    asm volatile(
        "mma.sync.aligned.m16n8k16.row.col.f32.bf16.bf16.f32 "
        "{%0,%1,%2,%3}, {%4,%5,%6,%7}, {%8,%9}, {%0,%1,%2,%3};"
        : "+f"(d[0]), "+f"(d[1]), "+f"(d[2]), "+f"(d[3])
        : "r"(a[0]), "r"(a[1]), "r"(a[2]), "r"(a[3]), "r"(b[0]), "r"(b[1]));
}
__device__ __forceinline__ void mma16816h(float* d, const uint32_t* a, const uint32_t* b) {
    asm volatile(
        "mma.sync.aligned.m16n8k16.row.col.f32.f16.f16.f32 "
        "{%0,%1,%2,%3}, {%4,%5,%6,%7}, {%8,%9}, {%0,%1,%2,%3};"
        : "+f"(d[0]), "+f"(d[1]), "+f"(d[2]), "+f"(d[3])
        : "r"(a[0]), "r"(a[1]), "r"(a[2]), "r"(a[3]), "r"(b[0]), "r"(b[1]));
}
__device__ __forceinline__ uint32_t smem_u32(const void* p) {
    uint32_t a;
    asm("{ .reg .u64 t; cvta.to.shared.u64 t, %1; cvt.u32.u64 %0, t; }" : "=r"(a) : "l"(p));
    return a;
}
__device__ __forceinline__ void cp16(uint32_t saddr, const void* g) {
    asm volatile("cp.async.cg.shared.global [%0], [%1], 16;" :: "r"(saddr), "l"(g));
}
__device__ __forceinline__ float4 h8_to_f4(uint2 u) {
    __half2 a = *reinterpret_cast<__half2*>(&u.x);
    __half2 b = *reinterpret_cast<__half2*>(&u.y);
    float2 fa = __half22float2(a), fb = __half22float2(b);
    return make_float4(fa.x, fa.y, fb.x, fb.y);
}
// fp16 frag store (single array at sh[0..8192))
__device__ __forceinline__ void frag_store_h(uint32_t* sh, int row, int c4, uint2 w) {
    int mb = row >> 4, rm = row & 15, g = rm & 7, r1 = rm >> 3;
    int ks = c4 >> 4, khalf = (c4 >> 3) & 1, t0 = (c4 >> 1) & 3;
    int base = ((mb * 8 + ks) * 32 + g * 4 + t0) * 4 + (r1 + 2 * khalf);
    sh[base] = w.x;
    sh[base + 4] = w.y;
}
// fp32 -> fp16 frag store (single rounding)
__device__ __forceinline__ void frag_store_f2h(uint32_t* sh, int row, int c4, float4 v) {
    __half2 H01 = __floats2half2_rn(v.x, v.y);
    __half2 H23 = __floats2half2_rn(v.z, v.w);
    uint2 w;
    w.x = *reinterpret_cast<uint32_t*>(&H01);
    w.y = *reinterpret_cast<uint32_t*>(&H23);
    frag_store_h(sh, row, c4, w);
}

// ---------------- prep kernels ----------------
__global__ void k_prep_encB(const float* __restrict__ Wd, const float* __restrict__ Wt,
                            uint32_t* __restrict__ oh, uint32_t* __restrict__ ol) {
    int i = blockIdx.x * blockDim.x + threadIdx.x;
    if (i >= 2 * 24 * 512) return;
    int enc = i >= 24 * 512;
    int wa = enc ? i - 24 * 512 : i;
    int c = wa >> 9, w = wa & 511;
    int r = w & 1, lane = (w >> 1) & 31, ks = (w >> 6) & 1, nb = w >> 7;
    int n = nb * 8 + (lane >> 2);
    int k = c * 32 + ks * 16 + r * 8 + (lane & 3) * 2;
    const float* W = enc ? Wt : Wd;
    float v0 = W[(size_t)k * 32 + n];
    float v1 = W[(size_t)(k + 1) * 32 + n];
    __nv_bfloat16 h0 = __float2bfloat16_rn(v0), h1 = __float2bfloat16_rn(v1);
    __nv_bfloat162 H(h0, h1);
    __nv_bfloat162 L = __floats2bfloat162_rn(v0 - __bfloat162float(h0), v1 - __bfloat162float(h1));
    oh[i] = *reinterpret_cast<uint32_t*>(&H);
    ol[i] = *reinterpret_cast<uint32_t*>(&L);
}
// all 8 chunks fp16
__global__ void k_prep_fragB(const float* __restrict__ rel, const float* __restrict__ root,
                             const float* __restrict__ Win, const float* __restrict__ Wo1,
                             uint32_t* __restrict__ ob) {
    int i = blockIdx.x * blockDim.x + threadIdx.x;
    if (i >= 8 * 8192) return;
    int c = i >> 13, w = i & 8191;
    int nb = w >> 9, ks = (w >> 6) & 7, lane = (w >> 1) & 31, rr = w & 1;
    int g = lane >> 2, t = lane & 3;
    int n = nb * 8 + g;
    int kl = ks * 16 + rr * 8 + t * 2;
    const float* src = (c < 5) ? (rel + (size_t)c * 16384)
                     : (c == 5) ? root : (c == 6) ? Win : Wo1;
    float v0 = src[kl * 128 + n];
    float v1 = src[(kl + 1) * 128 + n];
    __half2 P = __floats2half2_rn(v0, v1);
    ob[i] = *reinterpret_cast<uint32_t*>(&P);
}

// ---------------- CSR build ----------------
__global__ void k_zero_int(int* __restrict__ p, int n) {
    int i = blockIdx.x * blockDim.x + threadIdx.x;
    if (i < n) p[i] = 0;
}
__global__ void k_count(const int* __restrict__ ei, const int* __restrict__ et) {
    int e = blockIdx.x * blockDim.x + threadIdx.x;
    if (e < EE) atomicAdd(&g_bcnt[ei[EE + e] * RR + et[e]], 1);
}
__global__ void k_scan1() {
    __shared__ int sh[SCAN_T];
    int b = blockIdx.x, t = threadIdx.x;
    int base = b * SCAN_BLOCK + t * SCAN_ELT;
    int v[SCAN_ELT], sum = 0;
#pragma unroll
    for (int i = 0; i < SCAN_ELT; i++) {
        v[i] = (base + i < NBKT) ? g_bcnt[base + i] : 0;
        sum += v[i];
    }
    sh[t] = sum;
    __syncthreads();
    for (int off = 1; off < SCAN_T; off <<= 1) {
        int x = (t >= off) ? sh[t - off] : 0;
        __syncthreads();
        sh[t] += x;
        __syncthreads();
    }
    int excl = sh[t] - sum;
#pragma unroll
    for (int i = 0; i < SCAN_ELT; i++) {
        if (base + i < NBKT) g_rp[base + i] = excl;
        excl += v[i];
    }
    if (t == SCAN_T - 1) g_aux[b] = sh[t];
}
__global__ void k_scan2() {
    __shared__ int sh[256];
    int t = threadIdx.x;
    int v = (t < NSCB) ? g_aux[t] : 0;
    sh[t] = v;
    __syncthreads();
    for (int off = 1; off < 256; off <<= 1) {
        int x = (t >= off) ? sh[t - off] : 0;
        __syncthreads();
        sh[t] += x;
        __syncthreads();
    }
    g_aux[t] = sh[t] - v;
}
__global__ void k_scan3() {
    int i = blockIdx.x * blockDim.x + threadIdx.x;
    if (i < NBKT) {
        int v = g_rp[i] + g_aux[i / SCAN_BLOCK];
        g_rp[i] = v;
        g_wpos[i] = v;
        g_inv[i] = 1.f / (float)max(g_bcnt[i], 1);
    }
    if (i == 0) g_rp[NBKT] = EE;
}
__global__ void k_fill(const int* __restrict__ ei, const int* __restrict__ et) {
    int e = blockIdx.x * blockDim.x + threadIdx.x;
    if (e >= EE) return;
    int r = et[e];
    int b = ei[EE + e] * RR + r;
    int pos = atomicAdd(&g_wpos[b], 1);
    g_eidx[pos] = r * NN + ei[e];
    g_esc[pos] = g_inv[b];
}

// ---------------- small feature encoders (fp32 out) ----------------
__global__ void k_enc_small(const float* __restrict__ np_, const float* __restrict__ cp,
                            const float* __restrict__ Wnp, const float* __restrict__ bnp,
                            const float* __restrict__ Wcp, const float* __restrict__ bcp,
                            float* __restrict__ q) {
    int i = blockIdx.x * blockDim.x + threadIdx.x;
    if (i >= NN * 64) return;
    int n = i >> 6, c = i & 63;
    float s; int col;
    if (c < 32) {
        s = bnp[c];
#pragma unroll
        for (int k = 0; k < 6; k++) s += np_[n * 6 + k] * Wnp[k * 32 + c];
        col = 64 + c;
    } else {
        int cc = c - 32;
        s = bcp[cc];
#pragma unroll
        for (int k = 0; k < 11; k++) s += cp[n * 11 + k] * Wcp[k * 32 + cc];
        col = 96 + cc;
    }
    q[n * DD + col] = lrelu(s);
}

// flat CSR gather: out[dst] += sum over edges: esc[e] * Z[eidx[e]][:]   (Z fp16, out fp16 RMW)
__global__ void k_agg(const __half* __restrict__ Z, __half* __restrict__ out) {
    int w = (blockIdx.x * blockDim.x + threadIdx.x) >> 5;
    int lane = threadIdx.x & 31;
    if (w >= NN) return;
    uint2 av = *reinterpret_cast<const uint2*>(&out[(size_t)w * DD + lane * 4]);
    float4 acc = h8_to_f4(av);
    int s = g_rp[w * RR], e = g_rp[w * RR + RR];
    const __half* Zb = Z + lane * 4;
    float4 p0 = make_float4(0.f, 0.f, 0.f, 0.f);
    float4 p1 = make_float4(0.f, 0.f, 0.f, 0.f);
    float4 p2 = make_float4(0.f, 0.f, 0.f, 0.f);
    float4 p3 = make_float4(0.f, 0.f, 0.f, 0.f);
    int j = s;
    for (; j + 8 <= e; j += 8) {
        int i0 = g_eidx[j], i1 = g_eidx[j + 1], i2 = g_eidx[j + 2], i3 = g_eidx[j + 3];
        int i4 = g_eidx[j + 4], i5 = g_eidx[j + 5], i6 = g_eidx[j + 6], i7 = g_eidx[j + 7];
        float s0 = g_esc[j], s1 = g_esc[j + 1], s2 = g_esc[j + 2], s3 = g_esc[j + 3];
        float s4 = g_esc[j + 4], s5 = g_esc[j + 5], s6 = g_esc[j + 6], s7 = g_esc[j + 7];
        float4 a = h8_to_f4(*reinterpret_cast<const uint2*>(Zb + (size_t)i0 * DD));
        float4 bb = h8_to_f4(*reinterpret_cast<const uint2*>(Zb + (size_t)i1 * DD));
        float4 cc = h8_to_f4(*reinterpret_cast<const uint2*>(Zb + (size_t)i2 * DD));
        float4 dd = h8_to_f4(*reinterpret_cast<const uint2*>(Zb + (size_t)i3 * DD));
        float4 ee = h8_to_f4(*reinterpret_cast<const uint2*>(Zb + (size_t)i4 * DD));
        float4 ff = h8_to_f4(*reinterpret_cast<const uint2*>(Zb + (size_t)i5 * DD));
        float4 gg = h8_to_f4(*reinterpret_cast<const uint2*>(Zb + (size_t)i6 * DD));
        float4 hh = h8_to_f4(*reinterpret_cast<const uint2*>(Zb + (size_t)i7 * DD));
        p0.x += s0 * a.x; p0.y += s0 * a.y; p0.z += s0 * a.z; p0.w += s0 * a.w;
        p1.x += s1 * bb.x; p1.y += s1 * bb.y; p1.z += s1 * bb.z; p1.w += s1 * bb.w;
        p2.x += s2 * cc.x; p2.y += s2 * cc.y; p2.z += s2 * cc.z; p2.w += s2 * cc.w;
        p3.x += s3 * dd.x; p3.y += s3 * dd.y; p3.z += s3 * dd.z; p3.w += s3 * dd.w;
        p0.x += s4 * ee.x; p0.y += s4 * ee.y; p0.z += s4 * ee.z; p0.w += s4 * ee.w;
        p1.x += s5 * ff.x; p1.y += s5 * ff.y; p1.z += s5 * ff.z; p1.w += s5 * ff.w;
        p2.x += s6 * gg.x; p2.y += s6 * gg.y; p2.z += s6 * gg.z; p2.w += s6 * gg.w;
        p3.x += s7 * hh.x; p3.y += s7 * hh.y; p3.z += s7 * hh.z; p3.w += s7 * hh.w;
    }
    for (; j < e; j++) {
        float sc = g_esc[j];
        float4 a = h8_to_f4(*reinterpret_cast<const uint2*>(Zb + (size_t)g_eidx[j] * DD));
        p0.x += sc * a.x; p0.y += sc * a.y; p0.z += sc * a.z; p0.w += sc * a.w;
    }
    acc.x += p0.x + p1.x + p2.x + p3.x;
    acc.y += p0.y + p1.y + p2.y + p3.y;
    acc.z += p0.z + p1.z + p2.z + p3.z;
    acc.w += p0.w + p1.w + p2.w + p3.w;
    uint2 st;
    __half2 h01 = __floats2half2_rn(acc.x, acc.y);
    __half2 h23 = __floats2half2_rn(acc.z, acc.w);
    st.x = *reinterpret_cast<uint32_t*>(&h01);
    st.y = *reinterpret_cast<uint32_t*>(&h23);
    *reinterpret_cast<uint2*>(&out[(size_t)w * DD + lane * 4]) = st;
}

// ---------------- layer GEMM: fp16 A resident, fp16 B streamed; ONE mma term ----------------
__global__ __launch_bounds__(256)
void k_layer6(const __half* __restrict__ A, const uint32_t* __restrict__ gB,
              const float* __restrict__ bias, __half* __restrict__ Z, __half* __restrict__ Cout) {
    extern __shared__ uint32_t sm[];
    const int tid = threadIdx.x, lane = tid & 31, wid = tid >> 5;
    const int wm = wid >> 2, wn = wid & 3;
    const int n0 = blockIdx.x * 128;
    const uint32_t smb = smem_u32(sm);

#pragma unroll
    for (int it = 0; it < 16; it++) {
        int idx = it * 256 + tid;
        int row = idx >> 5, c4 = (idx & 31) * 4;
        int grow = n0 + row;
        uint2 w = make_uint2(0u, 0u);
        if (grow < NN) w = *reinterpret_cast<const uint2*>(&A[(size_t)grow * DD + c4]);
        frag_store_h(sm, row, c4, w);
    }

#define PF_Q(QC, S) do { \
    int cb_ = (QC) >> 2, q_ = (QC) & 3; \
    uint32_t dst_ = smb + ((8192u + (uint32_t)(S) * 2048u) << 2); \
    const uint32_t* b_ = gB + (size_t)cb_ * 8192 + q_ * 128; \
    _Pragma("unroll") \
    for (int it_ = 0; it_ < 2; it_++) { \
        int w4_ = (it_ * 256 + tid) * 4; \
        int nb_ = w4_ >> 7, u_ = w4_ & 127; \
        cp16(dst_ + ((uint32_t)w4_ << 2), b_ + nb_ * 512 + u_); \
    } \
} while (0)

    PF_Q(0, 0);
    asm volatile("cp.async.commit_group;" ::: "memory");

    float acc[4][4][4];
#pragma unroll 1
    for (int qc = 0; qc < 24; qc++) {
        const int s = qc & 1;
        if ((qc & 3) == 0) {
#pragma unroll
            for (int mb = 0; mb < 4; mb++)
#pragma unroll
                for (int nb = 0; nb < 4; nb++)
#pragma unroll
                    for (int q = 0; q < 4; q++) acc[mb][nb][q] = 0.f;
        }
        if (qc + 1 < 24) {
            PF_Q(qc + 1, s ^ 1);
            asm volatile("cp.async.commit_group;" ::: "memory");
            asm volatile("cp.async.wait_group 1;" ::: "memory");
        } else {
            asm volatile("cp.async.wait_group 0;" ::: "memory");
        }
        __syncthreads();

        const int bo = 8192 + s * 2048;
        const int ksg0 = (qc & 3) * 2;
#pragma unroll
        for (int ksq = 0; ksq < 2; ksq++) {
            uint32_t bf[4][2];
#pragma unroll
            for (int nb = 0; nb < 4; nb++) {
                int nbg = wn * 4 + nb;
                uint2 h = *reinterpret_cast<uint2*>(&sm[bo + ((nbg * 2 + ksq) * 32 + lane) * 2]);
                bf[nb][0] = h.x; bf[nb][1] = h.y;
            }
            const int ks = ksg0 + ksq;
#pragma unroll
            for (int mb = 0; mb < 4; mb++) {
                int mbg = wm * 4 + mb;
                uint4 a4 = *reinterpret_cast<uint4*>(&sm[((mbg * 8 + ks) * 32 + lane) * 4]);
                uint32_t ah[4] = {a4.x, a4.y, a4.z, a4.w};
#pragma unroll
                for (int nb = 0; nb < 4; nb++) mma16816h(acc[mb][nb], ah, bf[nb]);
            }
        }
        __syncthreads();
        if ((qc & 3) == 3) {
            const int cb = qc >> 2;
            int g = lane >> 2, t = lane & 3;
#pragma unroll
            for (int mb = 0; mb < 4; mb++) {
#pragma unroll
                for (int nb = 0; nb < 4; nb++) {
                    int col = (wn * 4 + nb) * 8 + 2 * t;
                    int row0 = n0 + wm * 64 + mb * 16 + g;
                    float c0 = acc[mb][nb][0], c1 = acc[mb][nb][1];
                    float c2 = acc[mb][nb][2], c3 = acc[mb][nb][3];
                    if (cb < 5) {
                        __half* Zp = Z + (size_t)cb * NN * DD;
                        if (row0 < NN)
                            *reinterpret_cast<__half2*>(&Zp[(size_t)row0 * DD + col]) = __floats2half2_rn(c0, c1);
                        if (row0 + 8 < NN)
                            *reinterpret_cast<__half2*>(&Zp[(size_t)(row0 + 8) * DD + col]) = __floats2half2_rn(c2, c3);
                    } else {
                        float b0 = bias[col], b1 = bias[col + 1];
                        if (row0 < NN)
                            *reinterpret_cast<__half2*>(&Cout[(size_t)row0 * DD + col]) = __floats2half2_rn(c0 + b0, c1 + b1);
                        if (row0 + 8 < NN)
                            *reinterpret_cast<__half2*>(&Cout[(size_t)(row0 + 8) * DD + col]) = __floats2half2_rn(c2 + b0, c3 + b1);
                    }
                }
            }
        }
    }
#undef PF_Q
}

// ---------------- square fp16 1-term GEMM ----------------
// HEAD=false: A fp32 (converted in-kernel), fp16 out + lrelu. HEAD=true: A fp16, fused W_o2 head.
template <bool HEAD>
__global__ __launch_bounds__(256)
void k_sq16(const float* __restrict__ Af, const __half* __restrict__ Ah,
            const uint32_t* __restrict__ gB,
            const float* __restrict__ bias, __half* __restrict__ CoutH, float* __restrict__ CoutF,
            const float* __restrict__ W2, const float* __restrict__ b2) {
    extern __shared__ uint32_t sm[];
    const int tid = threadIdx.x, lane = tid & 31, wid = tid >> 5;
    const int wm = wid >> 2, wn = wid & 3;
    const int n0 = blockIdx.x * 128;
    const uint32_t smb = smem_u32(sm);

#pragma unroll
    for (int it = 0; it < 8; it++) {
        int w = (it * 256 + tid) * 4;
        cp16(smb + ((8192u + (uint32_t)w) << 2), gB + w);
    }
    asm volatile("cp.async.commit_group;" ::: "memory");

#pragma unroll
    for (int it = 0; it < 16; it++) {
        int idx = it * 256 + tid;
        int row = idx >> 5, c4 = (idx & 31) * 4;
        int grow = n0 + row;
        if (HEAD) {
            uint2 w = make_uint2(0u, 0u);
            if (grow < NN) w = *reinterpret_cast<const uint2*>(&Ah[(size_t)grow * DD + c4]);
            frag_store_h(sm, row, c4, w);
        } else {
            float4 v = make_float4(0.f, 0.f, 0.f, 0.f);
            if (grow < NN) v = *reinterpret_cast<const float4*>(&Af[(size_t)grow * DD + c4]);
            frag_store_f2h(sm, row, c4, v);
        }
    }
    asm volatile("cp.async.wait_group 0;" ::: "memory");
    __syncthreads();

    float acc[4][4][4];
#pragma unroll
    for (int i = 0; i < 4; i++)
#pragma unroll
        for (int j = 0; j < 4; j++)
#pragma unroll
            for (int q = 0; q < 4; q++) acc[i][j][q] = 0.f;

#pragma unroll
    for (int ks = 0; ks < 8; ks++) {
        uint32_t bf[4][2];
#pragma unroll
        for (int nb = 0; nb < 4; nb++) {
            int nbg = wn * 4 + nb;
            uint2 h = *reinterpret_cast<uint2*>(&sm[8192 + ((nbg * 8 + ks) * 32 + lane) * 2]);
            bf[nb][0] = h.x; bf[nb][1] = h.y;
        }
#pragma unroll
        for (int mb = 0; mb < 4; mb++) {
            int mbg = wm * 4 + mb;
            uint4 a4 = *reinterpret_cast<uint4*>(&sm[((mbg * 8 + ks) * 32 + lane) * 4]);
            uint32_t ah[4] = {a4.x, a4.y, a4.z, a4.w};
#pragma unroll
            for (int nb = 0; nb < 4; nb++) mma16816h(acc[mb][nb], ah, bf[nb]);
        }
    }
    int g = lane >> 2, t = lane & 3;
    if (HEAD) {
        __syncthreads();
        float* zs = reinterpret_cast<float*>(&sm[8192]);
        float* w2s = reinterpret_cast<float*>(sm);
#pragma unroll
        for (int mb = 0; mb < 4; mb++) {
#pragma unroll
            for (int nb = 0; nb < 4; nb++) {
                int col = (wn * 4 + nb) * 8 + 2 * t;
                float b0 = bias[col], b1 = bias[col + 1];
                int rl = wm * 64 + mb * 16 + g;
                float c0 = lrelu(acc[mb][nb][0] + b0), c1 = lrelu(acc[mb][nb][1] + b1);
                float c2 = lrelu(acc[mb][nb][2] + b0), c3 = lrelu(acc[mb][nb][3] + b1);
                *reinterpret_cast<float2*>(&zs[rl * 132 + col]) = make_float2(c0, c1);
                *reinterpret_cast<float2*>(&zs[(rl + 8) * 132 + col]) = make_float2(c2, c3);
            }
        }
        if (tid < 256) w2s[tid] = W2[tid];
        if (tid < 2) w2s[256 + tid] = b2[tid];
        __syncthreads();
        if (tid < 128) {
            float o0 = 0.f, o1 = 0.f;
#pragma unroll 8
            for (int j = 0; j < 32; j++) {
                int cidx = (j + 2 * tid) & 31;
                float4 z4 = *reinterpret_cast<float4*>(&zs[tid * 132 + cidx * 4]);
                int cb8 = cidx * 8;
                o0 += z4.x * w2s[cb8] + z4.y * w2s[cb8 + 2] + z4.z * w2s[cb8 + 4] + z4.w * w2s[cb8 + 6];
                o1 += z4.x * w2s[cb8 + 1] + z4.y * w2s[cb8 + 3] + z4.z * w2s[cb8 + 5] + z4.w * w2s[cb8 + 7];
            }
            int grow = n0 + tid;
            if (grow < NN) {
                CoutF[(size_t)grow * 2 + 0] = o0 + w2s[256];
                CoutF[(size_t)grow * 2 + 1] = o1 + w2s[257];
            }
        }
    } else {
#pragma unroll
        for (int mb = 0; mb < 4; mb++) {
#pragma unroll
            for (int nb = 0; nb < 4; nb++) {
                int col = (wn * 4 + nb) * 8 + 2 * t;
                float b0 = bias[col], b1 = bias[col + 1];
                int row0 = n0 + wm * 64 + mb * 16 + g;
                float c0 = lrelu(acc[mb][nb][0] + b0), c1 = lrelu(acc[mb][nb][1] + b1);
                float c2 = lrelu(acc[mb][nb][2] + b0), c3 = lrelu(acc[mb][nb][3] + b1);
                if (row0 < NN)
                    *reinterpret_cast<__half2*>(&CoutH[(size_t)row0 * DD + col]) = __floats2half2_rn(c0, c1);
                if (row0 + 8 < NN)
                    *reinterpret_cast<__half2*>(&CoutH[(size_t)(row0 + 8) * DD + col]) = __floats2half2_rn(c2, c3);
            }
        }
    }
}

// ---------------- streaming encoder GEMM: 3-stage cp.async ring, fp32 out (R12-proven) ----------------
__global__ __launch_bounds__(256, 3)
void k_enc(const float* __restrict__ des, const float* __restrict__ tweet,
           const uint32_t* __restrict__ eBh_, const uint32_t* __restrict__ eBl_,
           const float* __restrict__ bd, const float* __restrict__ bt, float* __restrict__ C) {
    extern __shared__ uint32_t sm[];
    float* smf = reinterpret_cast<float*>(sm);
    const int tid = threadIdx.x, lane = tid & 31, wm = tid >> 5;
    const int g = lane >> 2, t = lane & 3;
    const int pair = blockIdx.y;
    const float* A0 = pair ? tweet : des;
    const uint32_t* eBh = eBh_ + pair * 12288;
    const uint32_t* eBl = eBl_ + pair * 12288;
    const float* bias = pair ? bt : bd;
    float* Cp = C + pair * 32;
    const int n0 = blockIdx.x * 128;
    const uint32_t smb = smem_u32(sm);

#define ISSUE(CC) do { \
    int s_ = (CC) % 3; \
    uint32_t ab_ = smb + (uint32_t)(s_ * 4608) * 4u; \
    int k0_ = (CC) * 32; \
    _Pragma("unroll") \
    for (int it_ = 0; it_ < 4; it_++) { \
        int idx_ = it_ * 256 + tid; \
        int row_ = idx_ >> 3, seg_ = idx_ & 7; \
        if (n0 + row_ < NN) \
            cp16(ab_ + (uint32_t)(row_ * 36 + seg_ * 4) * 4u, \
                 &A0[(size_t)(n0 + row_) * 768 + k0_ + seg_ * 4]); \
    } \
    { \
        uint32_t bb_ = smb + (uint32_t)(13824 + s_ * 1024) * 4u; \
        int m_ = tid >= 128; \
        int w4_ = (m_ ? tid - 128 : tid) * 4; \
        cp16(bb_ + (uint32_t)(m_ * 512 + w4_) * 4u, (m_ ? eBl : eBh) + (size_t)(CC) * 512 + w4_); \
    } \
} while (0)

    ISSUE(0);
    asm volatile("cp.async.commit_group;" ::: "memory");
    ISSUE(1);
    asm volatile("cp.async.commit_group;" ::: "memory");

    float acc[4][4];
#pragma unroll
    for (int j = 0; j < 4; j++)
#pragma unroll
        for (int q = 0; q < 4; q++) acc[j][q] = 0.f;

#pragma unroll 1
    for (int c = 0; c < 24; c++) {
        asm volatile("cp.async.wait_group 1;" ::: "memory");
        __syncthreads();
        if (c + 2 < 24) ISSUE(c + 2);
        asm volatile("cp.async.commit_group;" ::: "memory");

        const int rb = (c % 3) * 4608;
        const int bb = 13824 + (c % 3) * 1024;
#pragma unroll
        for (int ks = 0; ks < 2; ks++) {
            uint2 bh[4], bl[4];
#pragma unroll
            for (int nb = 0; nb < 4; nb++) {
                bh[nb] = *reinterpret_cast<uint2*>(&sm[bb + ((nb * 2 + ks) * 32 + lane) * 2]);
                bl[nb] = *reinterpret_cast<uint2*>(&sm[bb + 512 + ((nb * 2 + ks) * 32 + lane) * 2]);
            }
            uint32_t ah[4], al[4];
#pragma unroll
            for (int r = 0; r < 4; r++) {
                int row = wm * 16 + g + 8 * (r & 1);
                int kk = ks * 16 + 8 * (r >> 1) + t * 2;
                float2 f = *reinterpret_cast<float2*>(&smf[rb + row * 36 + kk]);
                __nv_bfloat16 h0 = __float2bfloat16_rn(f.x), h1 = __float2bfloat16_rn(f.y);
                __nv_bfloat162 H(h0, h1);
                __nv_bfloat162 L = __floats2bfloat162_rn(f.x - __bfloat162float(h0),
                                                         f.y - __bfloat162float(h1));
                ah[r] = *reinterpret_cast<uint32_t*>(&H);
                al[r] = *reinterpret_cast<uint32_t*>(&L);
            }
#pragma unroll
            for (int nb = 0; nb < 4; nb++) {
                mma16816(acc[nb], ah, reinterpret_cast<uint32_t*>(&bh[nb]));
                mma16816(acc[nb], ah, reinterpret_cast<uint32_t*>(&bl[nb]));
                mma16816(acc[nb], al, reinterpret_cast<uint32_t*>(&bh[nb]));
            }
        }
    }
#undef ISSUE

#pragma unroll
    for (int nb = 0; nb < 4; nb++) {
        int col = nb * 8 + 2 * t;
        float b0 = bias[col], b1 = bias[col + 1];
        int row0 = n0 + wm * 16 + g;
        float c0 = lrelu(acc[nb][0] + b0), c1 = lrelu(acc[nb][1] + b1);
        float c2 = lrelu(acc[nb][2] + b0), c3 = lrelu(acc[nb][3] + b1);
        if (row0 < NN) *reinterpret_cast<float2*>(&Cp[(size_t)row0 * DD + col]) = make_float2(c0, c1);
        if (row0 + 8 < NN) *reinterpret_cast<float2*>(&Cp[(size_t)(row0 + 8) * DD + col]) = make_float2(c2, c3);
    }
}

// ---------------- host launch ----------------
extern "C" void kernel_launch(void* const* d_in, const int* in_sizes, int n_in,
                              void* d_out, int out_size) {
    const float* des = (const float*)d_in[0];
    const float* tweet = (const float*)d_in[1];
    const float* np_ = (const float*)d_in[2];
    const float* cp = (const float*)d_in[3];
    const int* ei = (const int*)d_in[4];
    const int* et = (const int*)d_in[5];
    const float* W_des = (const float*)d_in[6];
    const float* b_des = (const float*)d_in[7];
    const float* W_tw = (const float*)d_in[8];
    const float* b_tw = (const float*)d_in[9];
    const float* W_np = (const float*)d_in[10];
    const float* b_np = (const float*)d_in[11];
    const float* W_cp = (const float*)d_in[12];
    const float* b_cp = (const float*)d_in[13];
    const float* W_in = (const float*)d_in[14];
    const float* b_in = (const float*)d_in[15];
    const float* rel_w = (const float*)d_in[16];
    const float* root_w = (const float*)d_in[17];
    const float* rgcn_b = (const float*)d_in[18];
    const float* W_o1 = (const float*)d_in[19];
    const float* b_o1 = (const float*)d_in[20];
    const float* W_o2 = (const float*)d_in[21];
    const float* b_o2 = (const float*)d_in[22];
    float* out = (float*)d_out;

    void *vy, *vx16, *vy16, *vZ, *veh, *vel, *vfb, *vbc;
    cudaGetSymbolAddress(&vy, g_y);
    cudaGetSymbolAddress(&vx16, g_x16);
    cudaGetSymbolAddress(&vy16, g_y16);
    cudaGetSymbolAddress(&vZ, g_Z);
    cudaGetSymbolAddress(&veh, g_eBh);
    cudaGetSymbolAddress(&vel, g_eBl);
    cudaGetSymbolAddress(&vfb, g_Bf);
    cudaGetSymbolAddress(&vbc, g_bcnt);
    float* py = (float*)vy;
    __half* px16 = (__half*)vx16;
    __half* py16 = (__half*)vy16;
    __half* pZ = (__half*)vZ;
    uint32_t* peh = (uint32_t*)veh;
    uint32_t* pel = (uint32_t*)vel;
    uint32_t* pFb = (uint32_t*)vfb;
    int* pbc = (int*)vbc;

    const int SMEM_ENC = 16896 * 4;    // 67.6 KB
    const int SMEM_SQ = 16384 * 4;     // 64 KB
    const int SMEM_HEAD = 25088 * 4;   // 100.4 KB
    const int SMEM_L6 = 12288 * 4;     // 48 KB
    cudaFuncSetAttribute(k_enc, cudaFuncAttributeMaxDynamicSharedMemorySize, SMEM_ENC);
    cudaFuncSetAttribute(k_sq16<false>, cudaFuncAttributeMaxDynamicSharedMemorySize, SMEM_SQ);
    cudaFuncSetAttribute(k_sq16<true>, cudaFuncAttributeMaxDynamicSharedMemorySize, SMEM_HEAD);
    cudaFuncSetAttribute(k_layer6, cudaFuncAttributeMaxDynamicSharedMemorySize, SMEM_L6);

    // 1-3: preps + small encoders; 4: k_enc (ncu capture slot)
    k_prep_encB<<<(2 * 24 * 512 + 255) / 256, 256>>>(W_des, W_tw, peh, pel);
    k_prep_fragB<<<256, 256>>>(rel_w, root_w, W_in, W_o1, pFb);
    k_enc_small<<<(NN * 64 + 255) / 256, 256>>>(np_, cp, W_np, b_np, W_cp, b_cp, py);
    k_enc<<<dim3(NTILE, 2), 256, SMEM_ENC>>>(des, tweet, peh, pel, b_des, b_tw, py);

    // CSR build
    k_zero_int<<<(NBKT + 255) / 256, 256>>>(pbc, NBKT);
    k_count<<<(EE + 255) / 256, 256>>>(ei, et);
    k_scan1<<<NSCB, SCAN_T>>>();
    k_scan2<<<1, 256>>>();
    k_scan3<<<(NBKT + 255) / 256, 256>>>();
    k_fill<<<(EE + 255) / 256, 256>>>(ei, et);

    // x0 = lrelu(y @ W_in + b_in) -> fp16 (A converted in-kernel, 1-term fp16 MMA)
    k_sq16<false><<<NTILE, 256, SMEM_SQ>>>(py, nullptr, pFb + FOFF_IN, b_in, px16, nullptr, nullptr, nullptr);

    // 4 RGCN layers (fp16 state)
    __half* cur = px16;
    __half* nxt = py16;
    for (int l = 0; l < 4; l++) {
        k_layer6<<<NTILE, 256, SMEM_L6>>>(cur, pFb + FOFF_LAYER, rgcn_b, pZ, nxt);
        k_agg<<<(NN * 32 + 255) / 256, 256>>>(pZ, nxt);
        __half* t = cur; cur = nxt; nxt = t;
    }

    // fused head (1-term fp16 MMA + W_o2 dot)
    k_sq16<true><<<NTILE, 256, SMEM_HEAD>>>(nullptr, cur, pFb + FOFF_O1, b_o1, nullptr, out, W_o2, b_o2);
}

// round 15
// speedup vs baseline: 1.4530x; 1.4530x over previous
#include <cuda_runtime.h>
#include <cuda_bf16.h>
#include <cuda_fp16.h>
#include <cstdint>

#define NN 50000
#define EE 800000
#define RR 5
#define DD 128
#define NTILE 391
#define NBKT (NN * RR)
#define SCAN_T 256
#define SCAN_ELT 8
#define SCAN_BLOCK (SCAN_T * SCAN_ELT)
#define NSCB ((NBKT + SCAN_BLOCK - 1) / SCAN_BLOCK)

// ---------------- device scratch ----------------
__device__ float  g_y[NN * DD];                 // encoder output (fp32)
__device__ __half g_x16[NN * DD];               // layer state ping
__device__ __half g_y16[NN * DD];               // layer state pong
__device__ __half g_Z[(size_t)RR * NN * DD];    // per-relation planes, fp16
__device__ int   g_bcnt[NBKT];
__device__ float g_inv[NBKT];
__device__ int   g_rp[NBKT + 1];
__device__ int   g_wpos[NBKT];
__device__ int   g_aux[256];
__device__ int   g_eidx[EE];    // et*NN + src
__device__ float g_esc[EE];     // inv[dst, et]

// encoder B fragment-ordered: [enc 2][chunk 24][512 words], bf16 hi/lo
__device__ uint32_t g_eBh[2 * 24 * 512];
__device__ uint32_t g_eBl[2 * 24 * 512];
// fragment-ordered fp16 B: chunks 0-4 rel_w, 5 root_w, 6 W_in, 7 W_o1; 8192 words each
#define FOFF_LAYER 0
#define FOFF_IN    (6 * 8192)
#define FOFF_O1    (7 * 8192)
__device__ uint32_t g_Bf[8 * 8192];

__device__ __forceinline__ float lrelu(float v) { return v > 0.f ? v : 0.01f * v; }

__device__ __forceinline__ void mma16816(float* d, const uint32_t* a, const uint32_t* b) {
    asm volatile(
        "mma.sync.aligned.m16n8k16.row.col.f32.bf16.bf16.f32 "
        "{%0,%1,%2,%3}, {%4,%5,%6,%7}, {%8,%9}, {%0,%1,%2,%3};"
        : "+f"(d[0]), "+f"(d[1]), "+f"(d[2]), "+f"(d[3])
        : "r"(a[0]), "r"(a[1]), "r"(a[2]), "r"(a[3]), "r"(b[0]), "r"(b[1]));
}
__device__ __forceinline__ void mma16816h(float* d, const uint32_t* a, const uint32_t* b) {
    asm volatile(
        "mma.sync.aligned.m16n8k16.row.col.f32.f16.f16.f32 "
        "{%0,%1,%2,%3}, {%4,%5,%6,%7}, {%8,%9}, {%0,%1,%2,%3};"
        : "+f"(d[0]), "+f"(d[1]), "+f"(d[2]), "+f"(d[3])
        : "r"(a[0]), "r"(a[1]), "r"(a[2]), "r"(a[3]), "r"(b[0]), "r"(b[1]));
}
__device__ __forceinline__ uint32_t smem_u32(const void* p) {
    uint32_t a;
    asm("{ .reg .u64 t; cvta.to.shared.u64 t, %1; cvt.u32.u64 %0, t; }" : "=r"(a) : "l"(p));
    return a;
}
__device__ __forceinline__ void cp16(uint32_t saddr, const void* g) {
    asm volatile("cp.async.cg.shared.global [%0], [%1], 16;" :: "r"(saddr), "l"(g));
}
__device__ __forceinline__ float4 h8_to_f4(uint2 u) {
    __half2 a = *reinterpret_cast<__half2*>(&u.x);
    __half2 b = *reinterpret_cast<__half2*>(&u.y);
    float2 fa = __half22float2(a), fb = __half22float2(b);
    return make_float4(fa.x, fa.y, fb.x, fb.y);
}
// fp16 frag store (single array at sh[0..8192))
__device__ __forceinline__ void frag_store_h(uint32_t* sh, int row, int c4, uint2 w) {
    int mb = row >> 4, rm = row & 15, g = rm & 7, r1 = rm >> 3;
    int ks = c4 >> 4, khalf = (c4 >> 3) & 1, t0 = (c4 >> 1) & 3;
    int base = ((mb * 8 + ks) * 32 + g * 4 + t0) * 4 + (r1 + 2 * khalf);
    sh[base] = w.x;
    sh[base + 4] = w.y;
}
// fp32 -> fp16 frag store (single rounding)
__device__ __forceinline__ void frag_store_f2h(uint32_t* sh, int row, int c4, float4 v) {
    __half2 H01 = __floats2half2_rn(v.x, v.y);
    __half2 H23 = __floats2half2_rn(v.z, v.w);
    uint2 w;
    w.x = *reinterpret_cast<uint32_t*>(&H01);
    w.y = *reinterpret_cast<uint32_t*>(&H23);
    frag_store_h(sh, row, c4, w);
}

// ---------------- prep kernels ----------------
__global__ void k_prep_encB(const float* __restrict__ Wd, const float* __restrict__ Wt,
                            uint32_t* __restrict__ oh, uint32_t* __restrict__ ol) {
    int i = blockIdx.x * blockDim.x + threadIdx.x;
    if (i >= 2 * 24 * 512) return;
    int enc = i >= 24 * 512;
    int wa = enc ? i - 24 * 512 : i;
    int c = wa >> 9, w = wa & 511;
    int r = w & 1, lane = (w >> 1) & 31, ks = (w >> 6) & 1, nb = w >> 7;
    int n = nb * 8 + (lane >> 2);
    int k = c * 32 + ks * 16 + r * 8 + (lane & 3) * 2;
    const float* W = enc ? Wt : Wd;
    float v0 = W[(size_t)k * 32 + n];
    float v1 = W[(size_t)(k + 1) * 32 + n];
    __nv_bfloat16 h0 = __float2bfloat16_rn(v0), h1 = __float2bfloat16_rn(v1);
    __nv_bfloat162 H(h0, h1);
    __nv_bfloat162 L = __floats2bfloat162_rn(v0 - __bfloat162float(h0), v1 - __bfloat162float(h1));
    oh[i] = *reinterpret_cast<uint32_t*>(&H);
    ol[i] = *reinterpret_cast<uint32_t*>(&L);
}
// all 8 chunks fp16
__global__ void k_prep_fragB(const float* __restrict__ rel, const float* __restrict__ root,
                             const float* __restrict__ Win, const float* __restrict__ Wo1,
                             uint32_t* __restrict__ ob) {
    int i = blockIdx.x * blockDim.x + threadIdx.x;
    if (i >= 8 * 8192) return;
    int c = i >> 13, w = i & 8191;
    int nb = w >> 9, ks = (w >> 6) & 7, lane = (w >> 1) & 31, rr = w & 1;
    int g = lane >> 2, t = lane & 3;
    int n = nb * 8 + g;
    int kl = ks * 16 + rr * 8 + t * 2;
    const float* src = (c < 5) ? (rel + (size_t)c * 16384)
                     : (c == 5) ? root : (c == 6) ? Win : Wo1;
    float v0 = src[kl * 128 + n];
    float v1 = src[(kl + 1) * 128 + n];
    __half2 P = __floats2half2_rn(v0, v1);
    ob[i] = *reinterpret_cast<uint32_t*>(&P);
}

// ---------------- CSR build ----------------
// zero bcnt (grid-stride) then count in one kernel launch pair replaced by fused prologue
__global__ void k_count(const int* __restrict__ ei, const int* __restrict__ et) {
    int i = blockIdx.x * blockDim.x + threadIdx.x;
    // phase 1: zero (grid covers EE >= NBKT)
    if (i < NBKT) g_bcnt[i] = 0;
    // grid-wide visibility of zeros before counting
    asm volatile("" ::: "memory");
    // use cooperative-free approach: separate pass below relies on a device-wide
    // dependency; we instead re-launch — see k_count2.
}
__global__ void k_count2(const int* __restrict__ ei, const int* __restrict__ et) {
    int e = blockIdx.x * blockDim.x + threadIdx.x;
    if (e < EE) atomicAdd(&g_bcnt[ei[EE + e] * RR + et[e]], 1);
}
__global__ void k_scan1() {
    __shared__ int sh[SCAN_T];
    int b = blockIdx.x, t = threadIdx.x;
    int base = b * SCAN_BLOCK + t * SCAN_ELT;
    int v[SCAN_ELT], sum = 0;
#pragma unroll
    for (int i = 0; i < SCAN_ELT; i++) {
        v[i] = (base + i < NBKT) ? g_bcnt[base + i] : 0;
        sum += v[i];
    }
    sh[t] = sum;
    __syncthreads();
    for (int off = 1; off < SCAN_T; off <<= 1) {
        int x = (t >= off) ? sh[t - off] : 0;
        __syncthreads();
        sh[t] += x;
        __syncthreads();
    }
    int excl = sh[t] - sum;
#pragma unroll
    for (int i = 0; i < SCAN_ELT; i++) {
        if (base + i < NBKT) g_rp[base + i] = excl;
        excl += v[i];
    }
    if (t == SCAN_T - 1) g_aux[b] = sh[t];
}
__global__ void k_scan2() {
    __shared__ int sh[256];
    int t = threadIdx.x;
    int v = (t < NSCB) ? g_aux[t] : 0;
    sh[t] = v;
    __syncthreads();
    for (int off = 1; off < 256; off <<= 1) {
        int x = (t >= off) ? sh[t - off] : 0;
        __syncthreads();
        sh[t] += x;
        __syncthreads();
    }
    g_aux[t] = sh[t] - v;
}
__global__ void k_scan3() {
    int i = blockIdx.x * blockDim.x + threadIdx.x;
    if (i < NBKT) {
        int v = g_rp[i] + g_aux[i / SCAN_BLOCK];
        g_rp[i] = v;
        g_wpos[i] = v;
        g_inv[i] = 1.f / (float)max(g_bcnt[i], 1);
    }
    if (i == 0) g_rp[NBKT] = EE;
}
__global__ void k_fill(const int* __restrict__ ei, const int* __restrict__ et) {
    int e = blockIdx.x * blockDim.x + threadIdx.x;
    if (e >= EE) return;
    int r = et[e];
    int b = ei[EE + e] * RR + r;
    int pos = atomicAdd(&g_wpos[b], 1);
    g_eidx[pos] = r * NN + ei[e];
    g_esc[pos] = g_inv[b];
}

// ---------------- small feature encoders (fp32 out) ----------------
__global__ void k_enc_small(const float* __restrict__ np_, const float* __restrict__ cp,
                            const float* __restrict__ Wnp, const float* __restrict__ bnp,
                            const float* __restrict__ Wcp, const float* __restrict__ bcp,
                            float* __restrict__ q) {
    int i = blockIdx.x * blockDim.x + threadIdx.x;
    if (i >= NN * 64) return;
    int n = i >> 6, c = i & 63;
    float s; int col;
    if (c < 32) {
        s = bnp[c];
#pragma unroll
        for (int k = 0; k < 6; k++) s += np_[n * 6 + k] * Wnp[k * 32 + c];
        col = 64 + c;
    } else {
        int cc = c - 32;
        s = bcp[cc];
#pragma unroll
        for (int k = 0; k < 11; k++) s += cp[n * 11 + k] * Wcp[k * 32 + cc];
        col = 96 + cc;
    }
    q[n * DD + col] = lrelu(s);
}

// flat CSR gather: out[dst] += sum over edges: esc[e] * Z[eidx[e]][:]   (Z fp16, out fp16 RMW)
__global__ void k_agg(const __half* __restrict__ Z, __half* __restrict__ out) {
    int w = (blockIdx.x * blockDim.x + threadIdx.x) >> 5;
    int lane = threadIdx.x & 31;
    if (w >= NN) return;
    uint2 av = *reinterpret_cast<const uint2*>(&out[(size_t)w * DD + lane * 4]);
    float4 acc = h8_to_f4(av);
    int s = g_rp[w * RR], e = g_rp[w * RR + RR];
    const __half* Zb = Z + lane * 4;
    float4 p0 = make_float4(0.f, 0.f, 0.f, 0.f);
    float4 p1 = make_float4(0.f, 0.f, 0.f, 0.f);
    float4 p2 = make_float4(0.f, 0.f, 0.f, 0.f);
    float4 p3 = make_float4(0.f, 0.f, 0.f, 0.f);
    int j = s;
    for (; j + 8 <= e; j += 8) {
        int i0 = g_eidx[j], i1 = g_eidx[j + 1], i2 = g_eidx[j + 2], i3 = g_eidx[j + 3];
        int i4 = g_eidx[j + 4], i5 = g_eidx[j + 5], i6 = g_eidx[j + 6], i7 = g_eidx[j + 7];
        float s0 = g_esc[j], s1 = g_esc[j + 1], s2 = g_esc[j + 2], s3 = g_esc[j + 3];
        float s4 = g_esc[j + 4], s5 = g_esc[j + 5], s6 = g_esc[j + 6], s7 = g_esc[j + 7];
        float4 a = h8_to_f4(*reinterpret_cast<const uint2*>(Zb + (size_t)i0 * DD));
        float4 bb = h8_to_f4(*reinterpret_cast<const uint2*>(Zb + (size_t)i1 * DD));
        float4 cc = h8_to_f4(*reinterpret_cast<const uint2*>(Zb + (size_t)i2 * DD));
        float4 dd = h8_to_f4(*reinterpret_cast<const uint2*>(Zb + (size_t)i3 * DD));
        float4 ee = h8_to_f4(*reinterpret_cast<const uint2*>(Zb + (size_t)i4 * DD));
        float4 ff = h8_to_f4(*reinterpret_cast<const uint2*>(Zb + (size_t)i5 * DD));
        float4 gg = h8_to_f4(*reinterpret_cast<const uint2*>(Zb + (size_t)i6 * DD));
        float4 hh = h8_to_f4(*reinterpret_cast<const uint2*>(Zb + (size_t)i7 * DD));
        p0.x += s0 * a.x; p0.y += s0 * a.y; p0.z += s0 * a.z; p0.w += s0 * a.w;
        p1.x += s1 * bb.x; p1.y += s1 * bb.y; p1.z += s1 * bb.z; p1.w += s1 * bb.w;
        p2.x += s2 * cc.x; p2.y += s2 * cc.y; p2.z += s2 * cc.z; p2.w += s2 * cc.w;
        p3.x += s3 * dd.x; p3.y += s3 * dd.y; p3.z += s3 * dd.z; p3.w += s3 * dd.w;
        p0.x += s4 * ee.x; p0.y += s4 * ee.y; p0.z += s4 * ee.z; p0.w += s4 * ee.w;
        p1.x += s5 * ff.x; p1.y += s5 * ff.y; p1.z += s5 * ff.z; p1.w += s5 * ff.w;
        p2.x += s6 * gg.x; p2.y += s6 * gg.y; p2.z += s6 * gg.z; p2.w += s6 * gg.w;
        p3.x += s7 * hh.x; p3.y += s7 * hh.y; p3.z += s7 * hh.z; p3.w += s7 * hh.w;
    }
    for (; j < e; j++) {
        float sc = g_esc[j];
        float4 a = h8_to_f4(*reinterpret_cast<const uint2*>(Zb + (size_t)g_eidx[j] * DD));
        p0.x += sc * a.x; p0.y += sc * a.y; p0.z += sc * a.z; p0.w += sc * a.w;
    }
    acc.x += p0.x + p1.x + p2.x + p3.x;
    acc.y += p0.y + p1.y + p2.y + p3.y;
    acc.z += p0.z + p1.z + p2.z + p3.z;
    acc.w += p0.w + p1.w + p2.w + p3.w;
    uint2 st;
    __half2 h01 = __floats2half2_rn(acc.x, acc.y);
    __half2 h23 = __floats2half2_rn(acc.z, acc.w);
    st.x = *reinterpret_cast<uint32_t*>(&h01);
    st.y = *reinterpret_cast<uint32_t*>(&h23);
    *reinterpret_cast<uint2*>(&out[(size_t)w * DD + lane * 4]) = st;
}

// ---------------- layer GEMM: fp16 A resident, fp16 B streamed; ONE mma term ----------------
__global__ __launch_bounds__(256)
void k_layer6(const __half* __restrict__ A, const uint32_t* __restrict__ gB,
              const float* __restrict__ bias, __half* __restrict__ Z, __half* __restrict__ Cout) {
    extern __shared__ uint32_t sm[];
    const int tid = threadIdx.x, lane = tid & 31, wid = tid >> 5;
    const int wm = wid >> 2, wn = wid & 3;
    const int n0 = blockIdx.x * 128;
    const uint32_t smb = smem_u32(sm);

#pragma unroll
    for (int it = 0; it < 16; it++) {
        int idx = it * 256 + tid;
        int row = idx >> 5, c4 = (idx & 31) * 4;
        int grow = n0 + row;
        uint2 w = make_uint2(0u, 0u);
        if (grow < NN) w = *reinterpret_cast<const uint2*>(&A[(size_t)grow * DD + c4]);
        frag_store_h(sm, row, c4, w);
    }

#define PF_Q(QC, S) do { \
    int cb_ = (QC) >> 2, q_ = (QC) & 3; \
    uint32_t dst_ = smb + ((8192u + (uint32_t)(S) * 2048u) << 2); \
    const uint32_t* b_ = gB + (size_t)cb_ * 8192 + q_ * 128; \
    _Pragma("unroll") \
    for (int it_ = 0; it_ < 2; it_++) { \
        int w4_ = (it_ * 256 + tid) * 4; \
        int nb_ = w4_ >> 7, u_ = w4_ & 127; \
        cp16(dst_ + ((uint32_t)w4_ << 2), b_ + nb_ * 512 + u_); \
    } \
} while (0)

    PF_Q(0, 0);
    asm volatile("cp.async.commit_group;" ::: "memory");

    float acc[4][4][4];
#pragma unroll 1
    for (int qc = 0; qc < 24; qc++) {
        const int s = qc & 1;
        if ((qc & 3) == 0) {
#pragma unroll
            for (int mb = 0; mb < 4; mb++)
#pragma unroll
                for (int nb = 0; nb < 4; nb++)
#pragma unroll
                    for (int q = 0; q < 4; q++) acc[mb][nb][q] = 0.f;
        }
        if (qc + 1 < 24) {
            PF_Q(qc + 1, s ^ 1);
            asm volatile("cp.async.commit_group;" ::: "memory");
            asm volatile("cp.async.wait_group 1;" ::: "memory");
        } else {
            asm volatile("cp.async.wait_group 0;" ::: "memory");
        }
        __syncthreads();

        const int bo = 8192 + s * 2048;
        const int ksg0 = (qc & 3) * 2;
#pragma unroll
        for (int ksq = 0; ksq < 2; ksq++) {
            uint32_t bf[4][2];
#pragma unroll
            for (int nb = 0; nb < 4; nb++) {
                int nbg = wn * 4 + nb;
                uint2 h = *reinterpret_cast<uint2*>(&sm[bo + ((nbg * 2 + ksq) * 32 + lane) * 2]);
                bf[nb][0] = h.x; bf[nb][1] = h.y;
            }
            const int ks = ksg0 + ksq;
#pragma unroll
            for (int mb = 0; mb < 4; mb++) {
                int mbg = wm * 4 + mb;
                uint4 a4 = *reinterpret_cast<uint4*>(&sm[((mbg * 8 + ks) * 32 + lane) * 4]);
                uint32_t ah[4] = {a4.x, a4.y, a4.z, a4.w};
#pragma unroll
                for (int nb = 0; nb < 4; nb++) mma16816h(acc[mb][nb], ah, bf[nb]);
            }
        }
        __syncthreads();
        if ((qc & 3) == 3) {
            const int cb = qc >> 2;
            int g = lane >> 2, t = lane & 3;
#pragma unroll
            for (int mb = 0; mb < 4; mb++) {
#pragma unroll
                for (int nb = 0; nb < 4; nb++) {
                    int col = (wn * 4 + nb) * 8 + 2 * t;
                    int row0 = n0 + wm * 64 + mb * 16 + g;
                    float c0 = acc[mb][nb][0], c1 = acc[mb][nb][1];
                    float c2 = acc[mb][nb][2], c3 = acc[mb][nb][3];
                    if (cb < 5) {
                        __half* Zp = Z + (size_t)cb * NN * DD;
                        if (row0 < NN)
                            *reinterpret_cast<__half2*>(&Zp[(size_t)row0 * DD + col]) = __floats2half2_rn(c0, c1);
                        if (row0 + 8 < NN)
                            *reinterpret_cast<__half2*>(&Zp[(size_t)(row0 + 8) * DD + col]) = __floats2half2_rn(c2, c3);
                    } else {
                        float b0 = bias[col], b1 = bias[col + 1];
                        if (row0 < NN)
                            *reinterpret_cast<__half2*>(&Cout[(size_t)row0 * DD + col]) = __floats2half2_rn(c0 + b0, c1 + b1);
                        if (row0 + 8 < NN)
                            *reinterpret_cast<__half2*>(&Cout[(size_t)(row0 + 8) * DD + col]) = __floats2half2_rn(c2 + b0, c3 + b1);
                    }
                }
            }
        }
    }
#undef PF_Q
}

// ---------------- square fp16 1-term GEMM ----------------
template <bool HEAD>
__global__ __launch_bounds__(256)
void k_sq16(const float* __restrict__ Af, const __half* __restrict__ Ah,
            const uint32_t* __restrict__ gB,
            const float* __restrict__ bias, __half* __restrict__ CoutH, float* __restrict__ CoutF,
            const float* __restrict__ W2, const float* __restrict__ b2) {
    extern __shared__ uint32_t sm[];
    const int tid = threadIdx.x, lane = tid & 31, wid = tid >> 5;
    const int wm = wid >> 2, wn = wid & 3;
    const int n0 = blockIdx.x * 128;
    const uint32_t smb = smem_u32(sm);

#pragma unroll
    for (int it = 0; it < 8; it++) {
        int w = (it * 256 + tid) * 4;
        cp16(smb + ((8192u + (uint32_t)w) << 2), gB + w);
    }
    asm volatile("cp.async.commit_group;" ::: "memory");

#pragma unroll
    for (int it = 0; it < 16; it++) {
        int idx = it * 256 + tid;
        int row = idx >> 5, c4 = (idx & 31) * 4;
        int grow = n0 + row;
        if (HEAD) {
            uint2 w = make_uint2(0u, 0u);
            if (grow < NN) w = *reinterpret_cast<const uint2*>(&Ah[(size_t)grow * DD + c4]);
            frag_store_h(sm, row, c4, w);
        } else {
            float4 v = make_float4(0.f, 0.f, 0.f, 0.f);
            if (grow < NN) v = *reinterpret_cast<const float4*>(&Af[(size_t)grow * DD + c4]);
            frag_store_f2h(sm, row, c4, v);
        }
    }
    asm volatile("cp.async.wait_group 0;" ::: "memory");
    __syncthreads();

    float acc[4][4][4];
#pragma unroll
    for (int i = 0; i < 4; i++)
#pragma unroll
        for (int j = 0; j < 4; j++)
#pragma unroll
            for (int q = 0; q < 4; q++) acc[i][j][q] = 0.f;

#pragma unroll
    for (int ks = 0; ks < 8; ks++) {
        uint32_t bf[4][2];
#pragma unroll
        for (int nb = 0; nb < 4; nb++) {
            int nbg = wn * 4 + nb;
            uint2 h = *reinterpret_cast<uint2*>(&sm[8192 + ((nbg * 8 + ks) * 32 + lane) * 2]);
            bf[nb][0] = h.x; bf[nb][1] = h.y;
        }
#pragma unroll
        for (int mb = 0; mb < 4; mb++) {
            int mbg = wm * 4 + mb;
            uint4 a4 = *reinterpret_cast<uint4*>(&sm[((mbg * 8 + ks) * 32 + lane) * 4]);
            uint32_t ah[4] = {a4.x, a4.y, a4.z, a4.w};
#pragma unroll
            for (int nb = 0; nb < 4; nb++) mma16816h(acc[mb][nb], ah, bf[nb]);
        }
    }
    int g = lane >> 2, t = lane & 3;
    if (HEAD) {
        __syncthreads();
        float* zs = reinterpret_cast<float*>(&sm[8192]);
        float* w2s = reinterpret_cast<float*>(sm);
#pragma unroll
        for (int mb = 0; mb < 4; mb++) {
#pragma unroll
            for (int nb = 0; nb < 4; nb++) {
                int col = (wn * 4 + nb) * 8 + 2 * t;
                float b0 = bias[col], b1 = bias[col + 1];
                int rl = wm * 64 + mb * 16 + g;
                float c0 = lrelu(acc[mb][nb][0] + b0), c1 = lrelu(acc[mb][nb][1] + b1);
                float c2 = lrelu(acc[mb][nb][2] + b0), c3 = lrelu(acc[mb][nb][3] + b1);
                *reinterpret_cast<float2*>(&zs[rl * 132 + col]) = make_float2(c0, c1);
                *reinterpret_cast<float2*>(&zs[(rl + 8) * 132 + col]) = make_float2(c2, c3);
            }
        }
        if (tid < 256) w2s[tid] = W2[tid];
        if (tid < 2) w2s[256 + tid] = b2[tid];
        __syncthreads();
        if (tid < 128) {
            float o0 = 0.f, o1 = 0.f;
#pragma unroll 8
            for (int j = 0; j < 32; j++) {
                int cidx = (j + 2 * tid) & 31;
                float4 z4 = *reinterpret_cast<float4*>(&zs[tid * 132 + cidx * 4]);
                int cb8 = cidx * 8;
                o0 += z4.x * w2s[cb8] + z4.y * w2s[cb8 + 2] + z4.z * w2s[cb8 + 4] + z4.w * w2s[cb8 + 6];
                o1 += z4.x * w2s[cb8 + 1] + z4.y * w2s[cb8 + 3] + z4.z * w2s[cb8 + 5] + z4.w * w2s[cb8 + 7];
            }
            int grow = n0 + tid;
            if (grow < NN) {
                CoutF[(size_t)grow * 2 + 0] = o0 + w2s[256];
                CoutF[(size_t)grow * 2 + 1] = o1 + w2s[257];
            }
        }
    } else {
#pragma unroll
        for (int mb = 0; mb < 4; mb++) {
#pragma unroll
            for (int nb = 0; nb < 4; nb++) {
                int col = (wn * 4 + nb) * 8 + 2 * t;
                float b0 = bias[col], b1 = bias[col + 1];
                int row0 = n0 + wm * 64 + mb * 16 + g;
                float c0 = lrelu(acc[mb][nb][0] + b0), c1 = lrelu(acc[mb][nb][1] + b1);
                float c2 = lrelu(acc[mb][nb][2] + b0), c3 = lrelu(acc[mb][nb][3] + b1);
                if (row0 < NN)
                    *reinterpret_cast<__half2*>(&CoutH[(size_t)row0 * DD + col]) = __floats2half2_rn(c0, c1);
                if (row0 + 8 < NN)
                    *reinterpret_cast<__half2*>(&CoutH[(size_t)(row0 + 8) * DD + col]) = __floats2half2_rn(c2, c3);
            }
        }
    }
}

// ---------------- streaming encoder GEMM: 3-stage cp.async ring, fp32 out ----------------
__global__ __launch_bounds__(256, 3)
void k_enc(const float* __restrict__ des, const float* __restrict__ tweet,
           const uint32_t* __restrict__ eBh_, const uint32_t* __restrict__ eBl_,
           const float* __restrict__ bd, const float* __restrict__ bt, float* __restrict__ C) {
    extern __shared__ uint32_t sm[];
    float* smf = reinterpret_cast<float*>(sm);
    const int tid = threadIdx.x, lane = tid & 31, wm = tid >> 5;
    const int g = lane >> 2, t = lane & 3;
    const int pair = blockIdx.y;
    const float* A0 = pair ? tweet : des;
    const uint32_t* eBh = eBh_ + pair * 12288;
    const uint32_t* eBl = eBl_ + pair * 12288;
    const float* bias = pair ? bt : bd;
    float* Cp = C + pair * 32;
    const int n0 = blockIdx.x * 128;
    const uint32_t smb = smem_u32(sm);

#define ISSUE(CC) do { \
    int s_ = (CC) % 3; \
    uint32_t ab_ = smb + (uint32_t)(s_ * 4608) * 4u; \
    int k0_ = (CC) * 32; \
    _Pragma("unroll") \
    for (int it_ = 0; it_ < 4; it_++) { \
        int idx_ = it_ * 256 + tid; \
        int row_ = idx_ >> 3, seg_ = idx_ & 7; \
        if (n0 + row_ < NN) \
            cp16(ab_ + (uint32_t)(row_ * 36 + seg_ * 4) * 4u, \
                 &A0[(size_t)(n0 + row_) * 768 + k0_ + seg_ * 4]); \
    } \
    { \
        uint32_t bb_ = smb + (uint32_t)(13824 + s_ * 1024) * 4u; \
        int m_ = tid >= 128; \
        int w4_ = (m_ ? tid - 128 : tid) * 4; \
        cp16(bb_ + (uint32_t)(m_ * 512 + w4_) * 4u, (m_ ? eBl : eBh) + (size_t)(CC) * 512 + w4_); \
    } \
} while (0)

    ISSUE(0);
    asm volatile("cp.async.commit_group;" ::: "memory");
    ISSUE(1);
    asm volatile("cp.async.commit_group;" ::: "memory");

    float acc[4][4];
#pragma unroll
    for (int j = 0; j < 4; j++)
#pragma unroll
        for (int q = 0; q < 4; q++) acc[j][q] = 0.f;

#pragma unroll 1
    for (int c = 0; c < 24; c++) {
        asm volatile("cp.async.wait_group 1;" ::: "memory");
        __syncthreads();
        if (c + 2 < 24) ISSUE(c + 2);
        asm volatile("cp.async.commit_group;" ::: "memory");

        const int rb = (c % 3) * 4608;
        const int bb = 13824 + (c % 3) * 1024;
#pragma unroll
        for (int ks = 0; ks < 2; ks++) {
            uint2 bh[4], bl[4];
#pragma unroll
            for (int nb = 0; nb < 4; nb++) {
                bh[nb] = *reinterpret_cast<uint2*>(&sm[bb + ((nb * 2 + ks) * 32 + lane) * 2]);
                bl[nb] = *reinterpret_cast<uint2*>(&sm[bb + 512 + ((nb * 2 + ks) * 32 + lane) * 2]);
            }
            uint32_t ah[4], al[4];
#pragma unroll
            for (int r = 0; r < 4; r++) {
                int row = wm * 16 + g + 8 * (r & 1);
                int kk = ks * 16 + 8 * (r >> 1) + t * 2;
                float2 f = *reinterpret_cast<float2*>(&smf[rb + row * 36 + kk]);
                __nv_bfloat16 h0 = __float2bfloat16_rn(f.x), h1 = __float2bfloat16_rn(f.y);
                __nv_bfloat162 H(h0, h1);
                __nv_bfloat162 L = __floats2bfloat162_rn(f.x - __bfloat162float(h0),
                                                         f.y - __bfloat162float(h1));
                ah[r] = *reinterpret_cast<uint32_t*>(&H);
                al[r] = *reinterpret_cast<uint32_t*>(&L);
            }
#pragma unroll
            for (int nb = 0; nb < 4; nb++) {
                mma16816(acc[nb], ah, reinterpret_cast<uint32_t*>(&bh[nb]));
                mma16816(acc[nb], ah, reinterpret_cast<uint32_t*>(&bl[nb]));
                mma16816(acc[nb], al, reinterpret_cast<uint32_t*>(&bh[nb]));
            }
        }
    }
#undef ISSUE

#pragma unroll
    for (int nb = 0; nb < 4; nb++) {
        int col = nb * 8 + 2 * t;
        float b0 = bias[col], b1 = bias[col + 1];
        int row0 = n0 + wm * 16 + g;
        float c0 = lrelu(acc[nb][0] + b0), c1 = lrelu(acc[nb][1] + b1);
        float c2 = lrelu(acc[nb][2] + b0), c3 = lrelu(acc[nb][3] + b1);
        if (row0 < NN) *reinterpret_cast<float2*>(&Cp[(size_t)row0 * DD + col]) = make_float2(c0, c1);
        if (row0 + 8 < NN) *reinterpret_cast<float2*>(&Cp[(size_t)(row0 + 8) * DD + col]) = make_float2(c2, c3);
    }
}

// ---------------- host launch ----------------
extern "C" void kernel_launch(void* const* d_in, const int* in_sizes, int n_in,
                              void* d_out, int out_size) {
    const float* des = (const float*)d_in[0];
    const float* tweet = (const float*)d_in[1];
    const float* np_ = (const float*)d_in[2];
    const float* cp = (const float*)d_in[3];
    const int* ei = (const int*)d_in[4];
    const int* et = (const int*)d_in[5];
    const float* W_des = (const float*)d_in[6];
    const float* b_des = (const float*)d_in[7];
    const float* W_tw = (const float*)d_in[8];
    const float* b_tw = (const float*)d_in[9];
    const float* W_np = (const float*)d_in[10];
    const float* b_np = (const float*)d_in[11];
    const float* W_cp = (const float*)d_in[12];
    const float* b_cp = (const float*)d_in[13];
    const float* W_in = (const float*)d_in[14];
    const float* b_in = (const float*)d_in[15];
    const float* rel_w = (const float*)d_in[16];
    const float* root_w = (const float*)d_in[17];
    const float* rgcn_b = (const float*)d_in[18];
    const float* W_o1 = (const float*)d_in[19];
    const float* b_o1 = (const float*)d_in[20];
    const float* W_o2 = (const float*)d_in[21];
    const float* b_o2 = (const float*)d_in[22];
    float* out = (float*)d_out;

    void *vy, *vx16, *vy16, *vZ, *veh, *vel, *vfb, *vbc;
    cudaGetSymbolAddress(&vy, g_y);
    cudaGetSymbolAddress(&vx16, g_x16);
    cudaGetSymbolAddress(&vy16, g_y16);
    cudaGetSymbolAddress(&vZ, g_Z);
    cudaGetSymbolAddress(&veh, g_eBh);
    cudaGetSymbolAddress(&vel, g_eBl);
    cudaGetSymbolAddress(&vfb, g_Bf);
    cudaGetSymbolAddress(&vbc, g_bcnt);
    float* py = (float*)vy;
    __half* px16 = (__half*)vx16;
    __half* py16 = (__half*)vy16;
    __half* pZ = (__half*)vZ;
    uint32_t* peh = (uint32_t*)veh;
    uint32_t* pel = (uint32_t*)vel;
    uint32_t* pFb = (uint32_t*)vfb;
    int* pbc = (int*)vbc;

    const int SMEM_ENC = 16896 * 4;    // 67.6 KB
    const int SMEM_SQ = 16384 * 4;     // 64 KB
    const int SMEM_HEAD = 25088 * 4;   // 100.4 KB
    const int SMEM_L6 = 12288 * 4;     // 48 KB
    cudaFuncSetAttribute(k_enc, cudaFuncAttributeMaxDynamicSharedMemorySize, SMEM_ENC);
    cudaFuncSetAttribute(k_sq16<false>, cudaFuncAttributeMaxDynamicSharedMemorySize, SMEM_SQ);
    cudaFuncSetAttribute(k_sq16<true>, cudaFuncAttributeMaxDynamicSharedMemorySize, SMEM_HEAD);
    cudaFuncSetAttribute(k_layer6, cudaFuncAttributeMaxDynamicSharedMemorySize, SMEM_L6);

    // 1-3: preps + small encoders; 4: k_enc (ncu capture slot / clock probe)
    k_prep_encB<<<(2 * 24 * 512 + 255) / 256, 256>>>(W_des, W_tw, peh, pel);
    k_prep_fragB<<<256, 256>>>(rel_w, root_w, W_in, W_o1, pFb);
    k_enc_small<<<(NN * 64 + 255) / 256, 256>>>(np_, cp, W_np, b_np, W_cp, b_cp, py);
    k_enc<<<dim3(NTILE, 2), 256, SMEM_ENC>>>(des, tweet, peh, pel, b_des, b_tw, py);

    // CSR build
    k_count<<<(NBKT + 255) / 256, 256>>>(ei, et);     // zero pass
    k_count2<<<(EE + 255) / 256, 256>>>(ei, et);      // count pass
    k_scan1<<<NSCB, SCAN_T>>>();
    k_scan2<<<1, 256>>>();
    k_scan3<<<(NBKT + 255) / 256, 256>>>();
    k_fill<<<(EE + 255) / 256, 256>>>(ei, et);

    // x0 = lrelu(y @ W_in + b_in) -> fp16 (A converted in-kernel, 1-term fp16 MMA)
    k_sq16<false><<<NTILE, 256, SMEM_SQ>>>(py, nullptr, pFb + FOFF_IN, b_in, px16, nullptr, nullptr, nullptr);

    // 4 RGCN layers (fp16 state)
    __half* cur = px16;
    __half* nxt = py16;
    for (int l = 0; l < 4; l++) {
        k_layer6<<<NTILE, 256, SMEM_L6>>>(cur, pFb + FOFF_LAYER, rgcn_b, pZ, nxt);
        k_agg<<<(NN * 32 + 255) / 256, 256>>>(pZ, nxt);
        __half* t = cur; cur = nxt; nxt = t;
    }

    // fused head (1-term fp16 MMA + W_o2 dot)
    k_sq16<true><<<NTILE, 256, SMEM_HEAD>>>(nullptr, cur, pFb + FOFF_O1, b_o1, nullptr, out, W_o2, b_o2);
}

// round 16
// speedup vs baseline: 1.4567x; 1.0025x over previous
#include <cuda_runtime.h>
#include <cuda_bf16.h>
#include <cuda_fp16.h>
#include <cstdint>

#define NN 50000
#define EE 800000
#define RR 5
#define DD 128
#define NTILE 391
#define NBKT (NN * RR)
#define SCAN_T 256
#define SCAN_ELT 8
#define SCAN_BLOCK (SCAN_T * SCAN_ELT)
#define NSCB ((NBKT + SCAN_BLOCK - 1) / SCAN_BLOCK)

// ---------------- device scratch ----------------
__device__ float  g_y[NN * DD];                 // encoder output (fp32)
__device__ __half g_x16[NN * DD];               // layer state ping
__device__ __half g_y16[NN * DD];               // layer state pong
__device__ __half g_Z[(size_t)RR * NN * DD];    // per-relation planes, fp16
__device__ int   g_bcnt[NBKT];
__device__ float g_inv[NBKT];
__device__ int   g_rp[NBKT + 1];
__device__ int   g_wpos[NBKT];
__device__ int   g_aux[256];
__device__ int   g_eidx[EE];    // et*NN + src
__device__ float g_esc[EE];     // inv[dst, et]

// encoder B fragment-ordered: [enc 2][chunk 24][512 words], bf16 hi/lo
__device__ uint32_t g_eBh[2 * 24 * 512];
__device__ uint32_t g_eBl[2 * 24 * 512];
// fragment-ordered fp16 B: chunks 0-4 rel_w, 5 root_w, 6 W_in, 7 W_o1; 8192 words each
#define FOFF_LAYER 0
#define FOFF_IN    (6 * 8192)
#define FOFF_O1    (7 * 8192)
__device__ uint32_t g_Bf[8 * 8192];

__device__ __forceinline__ float lrelu(float v) { return v > 0.f ? v : 0.01f * v; }

__device__ __forceinline__ void mma16816(float* d, const uint32_t* a, const uint32_t* b) {
    asm volatile(
        "mma.sync.aligned.m16n8k16.row.col.f32.bf16.bf16.f32 "
        "{%0,%1,%2,%3}, {%4,%5,%6,%7}, {%8,%9}, {%0,%1,%2,%3};"
        : "+f"(d[0]), "+f"(d[1]), "+f"(d[2]), "+f"(d[3])
        : "r"(a[0]), "r"(a[1]), "r"(a[2]), "r"(a[3]), "r"(b[0]), "r"(b[1]));
}
__device__ __forceinline__ void mma16816h(float* d, const uint32_t* a, const uint32_t* b) {
    asm volatile(
        "mma.sync.aligned.m16n8k16.row.col.f32.f16.f16.f32 "
        "{%0,%1,%2,%3}, {%4,%5,%6,%7}, {%8,%9}, {%0,%1,%2,%3};"
        : "+f"(d[0]), "+f"(d[1]), "+f"(d[2]), "+f"(d[3])
        : "r"(a[0]), "r"(a[1]), "r"(a[2]), "r"(a[3]), "r"(b[0]), "r"(b[1]));
}
__device__ __forceinline__ uint32_t smem_u32(const void* p) {
    uint32_t a;
    asm("{ .reg .u64 t; cvta.to.shared.u64 t, %1; cvt.u32.u64 %0, t; }" : "=r"(a) : "l"(p));
    return a;
}
__device__ __forceinline__ void cp16(uint32_t saddr, const void* g) {
    asm volatile("cp.async.cg.shared.global [%0], [%1], 16;" :: "r"(saddr), "l"(g));
}
__device__ __forceinline__ float4 h8_to_f4(uint2 u) {
    __half2 a = *reinterpret_cast<__half2*>(&u.x);
    __half2 b = *reinterpret_cast<__half2*>(&u.y);
    float2 fa = __half22float2(a), fb = __half22float2(b);
    return make_float4(fa.x, fa.y, fb.x, fb.y);
}
// fp16 frag store (single array at sh[0..8192))
__device__ __forceinline__ void frag_store_h(uint32_t* sh, int row, int c4, uint2 w) {
    int mb = row >> 4, rm = row & 15, g = rm & 7, r1 = rm >> 3;
    int ks = c4 >> 4, khalf = (c4 >> 3) & 1, t0 = (c4 >> 1) & 3;
    int base = ((mb * 8 + ks) * 32 + g * 4 + t0) * 4 + (r1 + 2 * khalf);
    sh[base] = w.x;
    sh[base + 4] = w.y;
}
// fp32 -> fp16 frag store (single rounding)
__device__ __forceinline__ void frag_store_f2h(uint32_t* sh, int row, int c4, float4 v) {
    __half2 H01 = __floats2half2_rn(v.x, v.y);
    __half2 H23 = __floats2half2_rn(v.z, v.w);
    uint2 w;
    w.x = *reinterpret_cast<uint32_t*>(&H01);
    w.y = *reinterpret_cast<uint32_t*>(&H23);
    frag_store_h(sh, row, c4, w);
}

// ---------------- prep kernels ----------------
__global__ void k_prep_encB(const float* __restrict__ Wd, const float* __restrict__ Wt,
                            uint32_t* __restrict__ oh, uint32_t* __restrict__ ol) {
    int i = blockIdx.x * blockDim.x + threadIdx.x;
    if (i >= 2 * 24 * 512) return;
    int enc = i >= 24 * 512;
    int wa = enc ? i - 24 * 512 : i;
    int c = wa >> 9, w = wa & 511;
    int r = w & 1, lane = (w >> 1) & 31, ks = (w >> 6) & 1, nb = w >> 7;
    int n = nb * 8 + (lane >> 2);
    int k = c * 32 + ks * 16 + r * 8 + (lane & 3) * 2;
    const float* W = enc ? Wt : Wd;
    float v0 = W[(size_t)k * 32 + n];
    float v1 = W[(size_t)(k + 1) * 32 + n];
    __nv_bfloat16 h0 = __float2bfloat16_rn(v0), h1 = __float2bfloat16_rn(v1);
    __nv_bfloat162 H(h0, h1);
    __nv_bfloat162 L = __floats2bfloat162_rn(v0 - __bfloat162float(h0), v1 - __bfloat162float(h1));
    oh[i] = *reinterpret_cast<uint32_t*>(&H);
    ol[i] = *reinterpret_cast<uint32_t*>(&L);
}
// all 8 chunks fp16; extended grid also zeroes g_bcnt
__global__ void k_prep_fragB(const float* __restrict__ rel, const float* __restrict__ root,
                             const float* __restrict__ Win, const float* __restrict__ Wo1,
                             uint32_t* __restrict__ ob) {
    int i = blockIdx.x * blockDim.x + threadIdx.x;
    if (i >= 8 * 8192) {
        int i2 = i - 8 * 8192;
        if (i2 < NBKT) g_bcnt[i2] = 0;
        return;
    }
    int c = i >> 13, w = i & 8191;
    int nb = w >> 9, ks = (w >> 6) & 7, lane = (w >> 1) & 31, rr = w & 1;
    int g = lane >> 2, t = lane & 3;
    int n = nb * 8 + g;
    int kl = ks * 16 + rr * 8 + t * 2;
    const float* src = (c < 5) ? (rel + (size_t)c * 16384)
                     : (c == 5) ? root : (c == 6) ? Win : Wo1;
    float v0 = src[kl * 128 + n];
    float v1 = src[(kl + 1) * 128 + n];
    __half2 P = __floats2half2_rn(v0, v1);
    ob[i] = *reinterpret_cast<uint32_t*>(&P);
}

// ---------------- CSR build ----------------
__global__ void k_count(const int* __restrict__ ei, const int* __restrict__ et) {
    int e = blockIdx.x * blockDim.x + threadIdx.x;
    if (e < EE) atomicAdd(&g_bcnt[ei[EE + e] * RR + et[e]], 1);
}
__global__ void k_scan1() {
    __shared__ int sh[SCAN_T];
    int b = blockIdx.x, t = threadIdx.x;
    int base = b * SCAN_BLOCK + t * SCAN_ELT;
    int v[SCAN_ELT], sum = 0;
#pragma unroll
    for (int i = 0; i < SCAN_ELT; i++) {
        v[i] = (base + i < NBKT) ? g_bcnt[base + i] : 0;
        sum += v[i];
    }
    sh[t] = sum;
    __syncthreads();
    for (int off = 1; off < SCAN_T; off <<= 1) {
        int x = (t >= off) ? sh[t - off] : 0;
        __syncthreads();
        sh[t] += x;
        __syncthreads();
    }
    int excl = sh[t] - sum;
#pragma unroll
    for (int i = 0; i < SCAN_ELT; i++) {
        if (base + i < NBKT) g_rp[base + i] = excl;
        excl += v[i];
    }
    if (t == SCAN_T - 1) g_aux[b] = sh[t];
}
__global__ void k_scan2() {
    __shared__ int sh[256];
    int t = threadIdx.x;
    int v = (t < NSCB) ? g_aux[t] : 0;
    sh[t] = v;
    __syncthreads();
    for (int off = 1; off < 256; off <<= 1) {
        int x = (t >= off) ? sh[t - off] : 0;
        __syncthreads();
        sh[t] += x;
        __syncthreads();
    }
    g_aux[t] = sh[t] - v;
}
__global__ void k_scan3() {
    int i = blockIdx.x * blockDim.x + threadIdx.x;
    if (i < NBKT) {
        int v = g_rp[i] + g_aux[i / SCAN_BLOCK];
        g_rp[i] = v;
        g_wpos[i] = v;
        g_inv[i] = 1.f / (float)max(g_bcnt[i], 1);
    }
    if (i == 0) g_rp[NBKT] = EE;
}
__global__ void k_fill(const int* __restrict__ ei, const int* __restrict__ et) {
    int e = blockIdx.x * blockDim.x + threadIdx.x;
    if (e >= EE) return;
    int r = et[e];
    int b = ei[EE + e] * RR + r;
    int pos = atomicAdd(&g_wpos[b], 1);
    g_eidx[pos] = r * NN + ei[e];
    g_esc[pos] = g_inv[b];
}

// ---------------- small feature encoders (fp32 out) ----------------
__global__ void k_enc_small(const float* __restrict__ np_, const float* __restrict__ cp,
                            const float* __restrict__ Wnp, const float* __restrict__ bnp,
                            const float* __restrict__ Wcp, const float* __restrict__ bcp,
                            float* __restrict__ q) {
    int i = blockIdx.x * blockDim.x + threadIdx.x;
    if (i >= NN * 64) return;
    int n = i >> 6, c = i & 63;
    float s; int col;
    if (c < 32) {
        s = bnp[c];
#pragma unroll
        for (int k = 0; k < 6; k++) s += np_[n * 6 + k] * Wnp[k * 32 + c];
        col = 64 + c;
    } else {
        int cc = c - 32;
        s = bcp[cc];
#pragma unroll
        for (int k = 0; k < 11; k++) s += cp[n * 11 + k] * Wcp[k * 32 + cc];
        col = 96 + cc;
    }
    q[n * DD + col] = lrelu(s);
}

// flat CSR gather: one warp per dst (32-thread blocks -> no block-retirement skew)
__global__ __launch_bounds__(32)
void k_agg(const __half* __restrict__ Z, __half* __restrict__ out) {
    int w = blockIdx.x;
    int lane = threadIdx.x;
    uint2 av = *reinterpret_cast<const uint2*>(&out[(size_t)w * DD + lane * 4]);
    float4 acc = h8_to_f4(av);
    int s = g_rp[w * RR], e = g_rp[w * RR + RR];
    const __half* Zb = Z + lane * 4;
    float4 p0 = make_float4(0.f, 0.f, 0.f, 0.f);
    float4 p1 = make_float4(0.f, 0.f, 0.f, 0.f);
    float4 p2 = make_float4(0.f, 0.f, 0.f, 0.f);
    float4 p3 = make_float4(0.f, 0.f, 0.f, 0.f);
    int j = s;
    for (; j + 8 <= e; j += 8) {
        int i0 = g_eidx[j], i1 = g_eidx[j + 1], i2 = g_eidx[j + 2], i3 = g_eidx[j + 3];
        int i4 = g_eidx[j + 4], i5 = g_eidx[j + 5], i6 = g_eidx[j + 6], i7 = g_eidx[j + 7];
        float s0 = g_esc[j], s1 = g_esc[j + 1], s2 = g_esc[j + 2], s3 = g_esc[j + 3];
        float s4 = g_esc[j + 4], s5 = g_esc[j + 5], s6 = g_esc[j + 6], s7 = g_esc[j + 7];
        float4 a = h8_to_f4(*reinterpret_cast<const uint2*>(Zb + (size_t)i0 * DD));
        float4 bb = h8_to_f4(*reinterpret_cast<const uint2*>(Zb + (size_t)i1 * DD));
        float4 cc = h8_to_f4(*reinterpret_cast<const uint2*>(Zb + (size_t)i2 * DD));
        float4 dd = h8_to_f4(*reinterpret_cast<const uint2*>(Zb + (size_t)i3 * DD));
        float4 ee = h8_to_f4(*reinterpret_cast<const uint2*>(Zb + (size_t)i4 * DD));
        float4 ff = h8_to_f4(*reinterpret_cast<const uint2*>(Zb + (size_t)i5 * DD));
        float4 gg = h8_to_f4(*reinterpret_cast<const uint2*>(Zb + (size_t)i6 * DD));
        float4 hh = h8_to_f4(*reinterpret_cast<const uint2*>(Zb + (size_t)i7 * DD));
        p0.x += s0 * a.x; p0.y += s0 * a.y; p0.z += s0 * a.z; p0.w += s0 * a.w;
        p1.x += s1 * bb.x; p1.y += s1 * bb.y; p1.z += s1 * bb.z; p1.w += s1 * bb.w;
        p2.x += s2 * cc.x; p2.y += s2 * cc.y; p2.z += s2 * cc.z; p2.w += s2 * cc.w;
        p3.x += s3 * dd.x; p3.y += s3 * dd.y; p3.z += s3 * dd.z; p3.w += s3 * dd.w;
        p0.x += s4 * ee.x; p0.y += s4 * ee.y; p0.z += s4 * ee.z; p0.w += s4 * ee.w;
        p1.x += s5 * ff.x; p1.y += s5 * ff.y; p1.z += s5 * ff.z; p1.w += s5 * ff.w;
        p2.x += s6 * gg.x; p2.y += s6 * gg.y; p2.z += s6 * gg.z; p2.w += s6 * gg.w;
        p3.x += s7 * hh.x; p3.y += s7 * hh.y; p3.z += s7 * hh.z; p3.w += s7 * hh.w;
    }
    for (; j < e; j++) {
        float sc = g_esc[j];
        float4 a = h8_to_f4(*reinterpret_cast<const uint2*>(Zb + (size_t)g_eidx[j] * DD));
        p0.x += sc * a.x; p0.y += sc * a.y; p0.z += sc * a.z; p0.w += sc * a.w;
    }
    acc.x += p0.x + p1.x + p2.x + p3.x;
    acc.y += p0.y + p1.y + p2.y + p3.y;
    acc.z += p0.z + p1.z + p2.z + p3.z;
    acc.w += p0.w + p1.w + p2.w + p3.w;
    uint2 st;
    __half2 h01 = __floats2half2_rn(acc.x, acc.y);
    __half2 h23 = __floats2half2_rn(acc.z, acc.w);
    st.x = *reinterpret_cast<uint32_t*>(&h01);
    st.y = *reinterpret_cast<uint32_t*>(&h23);
    *reinterpret_cast<uint2*>(&out[(size_t)w * DD + lane * 4]) = st;
}

// ---------------- layer GEMM: fp16 A resident, fp16 B streamed; ONE mma term ----------------
__global__ __launch_bounds__(256)
void k_layer6(const __half* __restrict__ A, const uint32_t* __restrict__ gB,
              const float* __restrict__ bias, __half* __restrict__ Z, __half* __restrict__ Cout) {
    extern __shared__ uint32_t sm[];
    const int tid = threadIdx.x, lane = tid & 31, wid = tid >> 5;
    const int wm = wid >> 2, wn = wid & 3;
    const int n0 = blockIdx.x * 128;
    const uint32_t smb = smem_u32(sm);

#pragma unroll
    for (int it = 0; it < 16; it++) {
        int idx = it * 256 + tid;
        int row = idx >> 5, c4 = (idx & 31) * 4;
        int grow = n0 + row;
        uint2 w = make_uint2(0u, 0u);
        if (grow < NN) w = *reinterpret_cast<const uint2*>(&A[(size_t)grow * DD + c4]);
        frag_store_h(sm, row, c4, w);
    }

#define PF_Q(QC, S) do { \
    int cb_ = (QC) >> 2, q_ = (QC) & 3; \
    uint32_t dst_ = smb + ((8192u + (uint32_t)(S) * 2048u) << 2); \
    const uint32_t* b_ = gB + (size_t)cb_ * 8192 + q_ * 128; \
    _Pragma("unroll") \
    for (int it_ = 0; it_ < 2; it_++) { \
        int w4_ = (it_ * 256 + tid) * 4; \
        int nb_ = w4_ >> 7, u_ = w4_ & 127; \
        cp16(dst_ + ((uint32_t)w4_ << 2), b_ + nb_ * 512 + u_); \
    } \
} while (0)

    PF_Q(0, 0);
    asm volatile("cp.async.commit_group;" ::: "memory");

    float acc[4][4][4];
#pragma unroll 1
    for (int qc = 0; qc < 24; qc++) {
        const int s = qc & 1;
        if ((qc & 3) == 0) {
#pragma unroll
            for (int mb = 0; mb < 4; mb++)
#pragma unroll
                for (int nb = 0; nb < 4; nb++)
#pragma unroll
                    for (int q = 0; q < 4; q++) acc[mb][nb][q] = 0.f;
        }
        if (qc + 1 < 24) {
            PF_Q(qc + 1, s ^ 1);
            asm volatile("cp.async.commit_group;" ::: "memory");
            asm volatile("cp.async.wait_group 1;" ::: "memory");
        } else {
            asm volatile("cp.async.wait_group 0;" ::: "memory");
        }
        __syncthreads();

        const int bo = 8192 + s * 2048;
        const int ksg0 = (qc & 3) * 2;
#pragma unroll
        for (int ksq = 0; ksq < 2; ksq++) {
            uint32_t bf[4][2];
#pragma unroll
            for (int nb = 0; nb < 4; nb++) {
                int nbg = wn * 4 + nb;
                uint2 h = *reinterpret_cast<uint2*>(&sm[bo + ((nbg * 2 + ksq) * 32 + lane) * 2]);
                bf[nb][0] = h.x; bf[nb][1] = h.y;
            }
            const int ks = ksg0 + ksq;
#pragma unroll
            for (int mb = 0; mb < 4; mb++) {
                int mbg = wm * 4 + mb;
                uint4 a4 = *reinterpret_cast<uint4*>(&sm[((mbg * 8 + ks) * 32 + lane) * 4]);
                uint32_t ah[4] = {a4.x, a4.y, a4.z, a4.w};
#pragma unroll
                for (int nb = 0; nb < 4; nb++) mma16816h(acc[mb][nb], ah, bf[nb]);
            }
        }
        __syncthreads();
        if ((qc & 3) == 3) {
            const int cb = qc >> 2;
            int g = lane >> 2, t = lane & 3;
#pragma unroll
            for (int mb = 0; mb < 4; mb++) {
#pragma unroll
                for (int nb = 0; nb < 4; nb++) {
                    int col = (wn * 4 + nb) * 8 + 2 * t;
                    int row0 = n0 + wm * 64 + mb * 16 + g;
                    float c0 = acc[mb][nb][0], c1 = acc[mb][nb][1];
                    float c2 = acc[mb][nb][2], c3 = acc[mb][nb][3];
                    if (cb < 5) {
                        __half* Zp = Z + (size_t)cb * NN * DD;
                        if (row0 < NN)
                            *reinterpret_cast<__half2*>(&Zp[(size_t)row0 * DD + col]) = __floats2half2_rn(c0, c1);
                        if (row0 + 8 < NN)
                            *reinterpret_cast<__half2*>(&Zp[(size_t)(row0 + 8) * DD + col]) = __floats2half2_rn(c2, c3);
                    } else {
                        float b0 = bias[col], b1 = bias[col + 1];
                        if (row0 < NN)
                            *reinterpret_cast<__half2*>(&Cout[(size_t)row0 * DD + col]) = __floats2half2_rn(c0 + b0, c1 + b1);
                        if (row0 + 8 < NN)
                            *reinterpret_cast<__half2*>(&Cout[(size_t)(row0 + 8) * DD + col]) = __floats2half2_rn(c2 + b0, c3 + b1);
                    }
                }
            }
        }
    }
#undef PF_Q
}

// ---------------- square fp16 1-term GEMM ----------------
template <bool HEAD>
__global__ __launch_bounds__(256)
void k_sq16(const float* __restrict__ Af, const __half* __restrict__ Ah,
            const uint32_t* __restrict__ gB,
            const float* __restrict__ bias, __half* __restrict__ CoutH, float* __restrict__ CoutF,
            const float* __restrict__ W2, const float* __restrict__ b2) {
    extern __shared__ uint32_t sm[];
    const int tid = threadIdx.x, lane = tid & 31, wid = tid >> 5;
    const int wm = wid >> 2, wn = wid & 3;
    const int n0 = blockIdx.x * 128;
    const uint32_t smb = smem_u32(sm);

#pragma unroll
    for (int it = 0; it < 8; it++) {
        int w = (it * 256 + tid) * 4;
        cp16(smb + ((8192u + (uint32_t)w) << 2), gB + w);
    }
    asm volatile("cp.async.commit_group;" ::: "memory");

#pragma unroll
    for (int it = 0; it < 16; it++) {
        int idx = it * 256 + tid;
        int row = idx >> 5, c4 = (idx & 31) * 4;
        int grow = n0 + row;
        if (HEAD) {
            uint2 w = make_uint2(0u, 0u);
            if (grow < NN) w = *reinterpret_cast<const uint2*>(&Ah[(size_t)grow * DD + c4]);
            frag_store_h(sm, row, c4, w);
        } else {
            float4 v = make_float4(0.f, 0.f, 0.f, 0.f);
            if (grow < NN) v = *reinterpret_cast<const float4*>(&Af[(size_t)grow * DD + c4]);
            frag_store_f2h(sm, row, c4, v);
        }
    }
    asm volatile("cp.async.wait_group 0;" ::: "memory");
    __syncthreads();

    float acc[4][4][4];
#pragma unroll
    for (int i = 0; i < 4; i++)
#pragma unroll
        for (int j = 0; j < 4; j++)
#pragma unroll
            for (int q = 0; q < 4; q++) acc[i][j][q] = 0.f;

#pragma unroll
    for (int ks = 0; ks < 8; ks++) {
        uint32_t bf[4][2];
#pragma unroll
        for (int nb = 0; nb < 4; nb++) {
            int nbg = wn * 4 + nb;
            uint2 h = *reinterpret_cast<uint2*>(&sm[8192 + ((nbg * 8 + ks) * 32 + lane) * 2]);
            bf[nb][0] = h.x; bf[nb][1] = h.y;
        }
#pragma unroll
        for (int mb = 0; mb < 4; mb++) {
            int mbg = wm * 4 + mb;
            uint4 a4 = *reinterpret_cast<uint4*>(&sm[((mbg * 8 + ks) * 32 + lane) * 4]);
            uint32_t ah[4] = {a4.x, a4.y, a4.z, a4.w};
#pragma unroll
            for (int nb = 0; nb < 4; nb++) mma16816h(acc[mb][nb], ah, bf[nb]);
        }
    }
    int g = lane >> 2, t = lane & 3;
    if (HEAD) {
        __syncthreads();
        float* zs = reinterpret_cast<float*>(&sm[8192]);
        float* w2s = reinterpret_cast<float*>(sm);
#pragma unroll
        for (int mb = 0; mb < 4; mb++) {
#pragma unroll
            for (int nb = 0; nb < 4; nb++) {
                int col = (wn * 4 + nb) * 8 + 2 * t;
                float b0 = bias[col], b1 = bias[col + 1];
                int rl = wm * 64 + mb * 16 + g;
                float c0 = lrelu(acc[mb][nb][0] + b0), c1 = lrelu(acc[mb][nb][1] + b1);
                float c2 = lrelu(acc[mb][nb][2] + b0), c3 = lrelu(acc[mb][nb][3] + b1);
                *reinterpret_cast<float2*>(&zs[rl * 132 + col]) = make_float2(c0, c1);
                *reinterpret_cast<float2*>(&zs[(rl + 8) * 132 + col]) = make_float2(c2, c3);
            }
        }
        if (tid < 256) w2s[tid] = W2[tid];
        if (tid < 2) w2s[256 + tid] = b2[tid];
        __syncthreads();
        if (tid < 128) {
            float o0 = 0.f, o1 = 0.f;
#pragma unroll 8
            for (int j = 0; j < 32; j++) {
                int cidx = (j + 2 * tid) & 31;
                float4 z4 = *reinterpret_cast<float4*>(&zs[tid * 132 + cidx * 4]);
                int cb8 = cidx * 8;
                o0 += z4.x * w2s[cb8] + z4.y * w2s[cb8 + 2] + z4.z * w2s[cb8 + 4] + z4.w * w2s[cb8 + 6];
                o1 += z4.x * w2s[cb8 + 1] + z4.y * w2s[cb8 + 3] + z4.z * w2s[cb8 + 5] + z4.w * w2s[cb8 + 7];
            }
            int grow = n0 + tid;
            if (grow < NN) {
                CoutF[(size_t)grow * 2 + 0] = o0 + w2s[256];
                CoutF[(size_t)grow * 2 + 1] = o1 + w2s[257];
            }
        }
    } else {
#pragma unroll
        for (int mb = 0; mb < 4; mb++) {
#pragma unroll
            for (int nb = 0; nb < 4; nb++) {
                int col = (wn * 4 + nb) * 8 + 2 * t;
                float b0 = bias[col], b1 = bias[col + 1];
                int row0 = n0 + wm * 64 + mb * 16 + g;
                float c0 = lrelu(acc[mb][nb][0] + b0), c1 = lrelu(acc[mb][nb][1] + b1);
                float c2 = lrelu(acc[mb][nb][2] + b0), c3 = lrelu(acc[mb][nb][3] + b1);
                if (row0 < NN)
                    *reinterpret_cast<__half2*>(&CoutH[(size_t)row0 * DD + col]) = __floats2half2_rn(c0, c1);
                if (row0 + 8 < NN)
                    *reinterpret_cast<__half2*>(&CoutH[(size_t)(row0 + 8) * DD + col]) = __floats2half2_rn(c2, c3);
            }
        }
    }
}

// ---------------- streaming encoder GEMM: 3-stage cp.async ring, fp32 out ----------------
__global__ __launch_bounds__(256, 3)
void k_enc(const float* __restrict__ des, const float* __restrict__ tweet,
           const uint32_t* __restrict__ eBh_, const uint32_t* __restrict__ eBl_,
           const float* __restrict__ bd, const float* __restrict__ bt, float* __restrict__ C) {
    extern __shared__ uint32_t sm[];
    float* smf = reinterpret_cast<float*>(sm);
    const int tid = threadIdx.x, lane = tid & 31, wm = tid >> 5;
    const int g = lane >> 2, t = lane & 3;
    const int pair = blockIdx.y;
    const float* A0 = pair ? tweet : des;
    const uint32_t* eBh = eBh_ + pair * 12288;
    const uint32_t* eBl = eBl_ + pair * 12288;
    const float* bias = pair ? bt : bd;
    float* Cp = C + pair * 32;
    const int n0 = blockIdx.x * 128;
    const uint32_t smb = smem_u32(sm);

#define ISSUE(CC) do { \
    int s_ = (CC) % 3; \
    uint32_t ab_ = smb + (uint32_t)(s_ * 4608) * 4u; \
    int k0_ = (CC) * 32; \
    _Pragma("unroll") \
    for (int it_ = 0; it_ < 4; it_++) { \
        int idx_ = it_ * 256 + tid; \
        int row_ = idx_ >> 3, seg_ = idx_ & 7; \
        if (n0 + row_ < NN) \
            cp16(ab_ + (uint32_t)(row_ * 36 + seg_ * 4) * 4u, \
                 &A0[(size_t)(n0 + row_) * 768 + k0_ + seg_ * 4]); \
    } \
    { \
        uint32_t bb_ = smb + (uint32_t)(13824 + s_ * 1024) * 4u; \
        int m_ = tid >= 128; \
        int w4_ = (m_ ? tid - 128 : tid) * 4; \
        cp16(bb_ + (uint32_t)(m_ * 512 + w4_) * 4u, (m_ ? eBl : eBh) + (size_t)(CC) * 512 + w4_); \
    } \
} while (0)

    ISSUE(0);
    asm volatile("cp.async.commit_group;" ::: "memory");
    ISSUE(1);
    asm volatile("cp.async.commit_group;" ::: "memory");

    float acc[4][4];
#pragma unroll
    for (int j = 0; j < 4; j++)
#pragma unroll
        for (int q = 0; q < 4; q++) acc[j][q] = 0.f;

#pragma unroll 1
    for (int c = 0; c < 24; c++) {
        asm volatile("cp.async.wait_group 1;" ::: "memory");
        __syncthreads();
        if (c + 2 < 24) ISSUE(c + 2);
        asm volatile("cp.async.commit_group;" ::: "memory");

        const int rb = (c % 3) * 4608;
        const int bb = 13824 + (c % 3) * 1024;
#pragma unroll
        for (int ks = 0; ks < 2; ks++) {
            uint2 bh[4], bl[4];
#pragma unroll
            for (int nb = 0; nb < 4; nb++) {
                bh[nb] = *reinterpret_cast<uint2*>(&sm[bb + ((nb * 2 + ks) * 32 + lane) * 2]);
                bl[nb] = *reinterpret_cast<uint2*>(&sm[bb + 512 + ((nb * 2 + ks) * 32 + lane) * 2]);
            }
            uint32_t ah[4], al[4];
#pragma unroll
            for (int r = 0; r < 4; r++) {
                int row = wm * 16 + g + 8 * (r & 1);
                int kk = ks * 16 + 8 * (r >> 1) + t * 2;
                float2 f = *reinterpret_cast<float2*>(&smf[rb + row * 36 + kk]);
                __nv_bfloat16 h0 = __float2bfloat16_rn(f.x), h1 = __float2bfloat16_rn(f.y);
                __nv_bfloat162 H(h0, h1);
                __nv_bfloat162 L = __floats2bfloat162_rn(f.x - __bfloat162float(h0),
                                                         f.y - __bfloat162float(h1));
                ah[r] = *reinterpret_cast<uint32_t*>(&H);
                al[r] = *reinterpret_cast<uint32_t*>(&L);
            }
#pragma unroll
            for (int nb = 0; nb < 4; nb++) {
                mma16816(acc[nb], ah, reinterpret_cast<uint32_t*>(&bh[nb]));
                mma16816(acc[nb], ah, reinterpret_cast<uint32_t*>(&bl[nb]));
                mma16816(acc[nb], al, reinterpret_cast<uint32_t*>(&bh[nb]));
            }
        }
    }
#undef ISSUE

#pragma unroll
    for (int nb = 0; nb < 4; nb++) {
        int col = nb * 8 + 2 * t;
        float b0 = bias[col], b1 = bias[col + 1];
        int row0 = n0 + wm * 16 + g;
        float c0 = lrelu(acc[nb][0] + b0), c1 = lrelu(acc[nb][1] + b1);
        float c2 = lrelu(acc[nb][2] + b0), c3 = lrelu(acc[nb][3] + b1);
        if (row0 < NN) *reinterpret_cast<float2*>(&Cp[(size_t)row0 * DD + col]) = make_float2(c0, c1);
        if (row0 + 8 < NN) *reinterpret_cast<float2*>(&Cp[(size_t)(row0 + 8) * DD + col]) = make_float2(c2, c3);
    }
}

// ---------------- host launch ----------------
extern "C" void kernel_launch(void* const* d_in, const int* in_sizes, int n_in,
                              void* d_out, int out_size) {
    const float* des = (const float*)d_in[0];
    const float* tweet = (const float*)d_in[1];
    const float* np_ = (const float*)d_in[2];
    const float* cp = (const float*)d_in[3];
    const int* ei = (const int*)d_in[4];
    const int* et = (const int*)d_in[5];
    const float* W_des = (const float*)d_in[6];
    const float* b_des = (const float*)d_in[7];
    const float* W_tw = (const float*)d_in[8];
    const float* b_tw = (const float*)d_in[9];
    const float* W_np = (const float*)d_in[10];
    const float* b_np = (const float*)d_in[11];
    const float* W_cp = (const float*)d_in[12];
    const float* b_cp = (const float*)d_in[13];
    const float* W_in = (const float*)d_in[14];
    const float* b_in = (const float*)d_in[15];
    const float* rel_w = (const float*)d_in[16];
    const float* root_w = (const float*)d_in[17];
    const float* rgcn_b = (const float*)d_in[18];
    const float* W_o1 = (const float*)d_in[19];
    const float* b_o1 = (const float*)d_in[20];
    const float* W_o2 = (const float*)d_in[21];
    const float* b_o2 = (const float*)d_in[22];
    float* out = (float*)d_out;

    void *vy, *vx16, *vy16, *vZ, *veh, *vel, *vfb;
    cudaGetSymbolAddress(&vy, g_y);
    cudaGetSymbolAddress(&vx16, g_x16);
    cudaGetSymbolAddress(&vy16, g_y16);
    cudaGetSymbolAddress(&vZ, g_Z);
    cudaGetSymbolAddress(&veh, g_eBh);
    cudaGetSymbolAddress(&vel, g_eBl);
    cudaGetSymbolAddress(&vfb, g_Bf);
    float* py = (float*)vy;
    __half* px16 = (__half*)vx16;
    __half* py16 = (__half*)vy16;
    __half* pZ = (__half*)vZ;
    uint32_t* peh = (uint32_t*)veh;
    uint32_t* pel = (uint32_t*)vel;
    uint32_t* pFb = (uint32_t*)vfb;

    const int SMEM_ENC = 16896 * 4;    // 67.6 KB
    const int SMEM_SQ = 16384 * 4;     // 64 KB
    const int SMEM_HEAD = 25088 * 4;   // 100.4 KB
    const int SMEM_L6 = 12288 * 4;     // 48 KB
    cudaFuncSetAttribute(k_enc, cudaFuncAttributeMaxDynamicSharedMemorySize, SMEM_ENC);
    cudaFuncSetAttribute(k_sq16<false>, cudaFuncAttributeMaxDynamicSharedMemorySize, SMEM_SQ);
    cudaFuncSetAttribute(k_sq16<true>, cudaFuncAttributeMaxDynamicSharedMemorySize, SMEM_HEAD);
    cudaFuncSetAttribute(k_layer6, cudaFuncAttributeMaxDynamicSharedMemorySize, SMEM_L6);

    // 1-3: preps (fragB also zeroes bcnt) + small encoders; 4: k_enc (clock probe)
    k_prep_encB<<<(2 * 24 * 512 + 255) / 256, 256>>>(W_des, W_tw, peh, pel);
    k_prep_fragB<<<(8 * 8192 + NBKT + 255) / 256, 256>>>(rel_w, root_w, W_in, W_o1, pFb);
    k_enc_small<<<(NN * 64 + 255) / 256, 256>>>(np_, cp, W_np, b_np, W_cp, b_cp, py);
    k_enc<<<dim3(NTILE, 2), 256, SMEM_ENC>>>(des, tweet, peh, pel, b_des, b_tw, py);

    // CSR build
    k_count<<<(EE + 255) / 256, 256>>>(ei, et);
    k_scan1<<<NSCB, SCAN_T>>>();
    k_scan2<<<1, 256>>>();
    k_scan3<<<(NBKT + 255) / 256, 256>>>();
    k_fill<<<(EE + 255) / 256, 256>>>(ei, et);

    // x0 = lrelu(y @ W_in + b_in) -> fp16 (A converted in-kernel, 1-term fp16 MMA)
    k_sq16<false><<<NTILE, 256, SMEM_SQ>>>(py, nullptr, pFb + FOFF_IN, b_in, px16, nullptr, nullptr, nullptr);

    // 4 RGCN layers (fp16 state)
    __half* cur = px16;
    __half* nxt = py16;
    for (int l = 0; l < 4; l++) {
        k_layer6<<<NTILE, 256, SMEM_L6>>>(cur, pFb + FOFF_LAYER, rgcn_b, pZ, nxt);
        k_agg<<<NN, 32>>>(pZ, nxt);
        __half* t = cur; cur = nxt; nxt = t;
    }

    // fused head (1-term fp16 MMA + W_o2 dot)
    k_sq16<true><<<NTILE, 256, SMEM_HEAD>>>(nullptr, cur, pFb + FOFF_O1, b_o1, nullptr, out, W_o2, b_o2);
}